// round 3
// baseline (speedup 1.0000x reference)
#include <cuda_runtime.h>
#include <math_constants.h>

#define N_NODES 50000
#define N_EDGES 1200000
#define N_GRAPHS 512
#define D1 64
#define NF 92
#define NG 50
#define BN_EPS 1e-5f
#define LOG2F_C 0.6931471805599453f

typedef unsigned long long ull;

// -------------------- device scratch --------------------
__device__ float g_out[N_NODES * D1];
__device__ float g_h[N_NODES * D1];
__device__ float g_agg[N_NODES * D1];
__device__ float g_bnstats[2 * D1];
__device__ float g_pool[N_GRAPHS * D1];
__device__ float g_cnt[N_GRAPHS];
__device__ int   g_hist[N_NODES];
__device__ int   g_eperm[N_EDGES];
// dst-sorted edge data (materialized once per call)
__device__ float g_EAs[(size_t)N_EDGES * NG];   // 240MB
__device__ float g_Cs[N_EDGES];
__device__ int   g_srcs[N_EDGES];
__device__ int   g_dsts[N_EDGES];

// -------------------- helpers --------------------
__device__ __forceinline__ ull ffma2(ull a, ull b, ull c) {
    ull d;
    asm("fma.rn.f32x2 %0, %1, %2, %3;" : "=l"(d) : "l"(a), "l"(b), "l"(c));
    return d;
}
__device__ __forceinline__ float f2lo(ull v) { return __uint_as_float((unsigned)(v & 0xffffffffull)); }
__device__ __forceinline__ float f2hi(ull v) { return __uint_as_float((unsigned)(v >> 32)); }

__device__ __forceinline__ float sspf(float v) {
    return fmaxf(v, 0.f) + __logf(1.f + __expf(-fabsf(v))) - LOG2F_C;
}

__device__ __forceinline__ void red4(float* p, float4 v) {
    asm volatile("red.global.add.v4.f32 [%0], {%1,%2,%3,%4};"
                 :: "l"(p), "f"(v.x), "f"(v.y), "f"(v.z), "f"(v.w) : "memory");
}

// =====================================================================
// counting sort by dst
// =====================================================================
__global__ void k_hist(const int* __restrict__ ei) {
    int i = blockIdx.x * blockDim.x + threadIdx.x;
    if (i < N_EDGES) atomicAdd(&g_hist[ei[N_EDGES + i]], 1);
}

__global__ __launch_bounds__(1024) void k_scan() {
    __shared__ int ss[1024];
    int t = threadIdx.x;
    int lo = t * 49;
    int hi = min(lo + 49, N_NODES);
    int s = 0;
    for (int b = lo; b < hi; b++) s += g_hist[b];
    ss[t] = s;
    __syncthreads();
    for (int off = 1; off < 1024; off <<= 1) {
        int v = (t >= off) ? ss[t - off] : 0;
        __syncthreads();
        ss[t] += v;
        __syncthreads();
    }
    int run = ss[t] - s;
    for (int b = lo; b < hi; b++) {
        int c = g_hist[b];
        g_hist[b] = run;
        run += c;
    }
}

__global__ void k_scatter(const int* __restrict__ ei) {
    int i = blockIdx.x * blockDim.x + threadIdx.x;
    if (i < N_EDGES) {
        int pos = atomicAdd(&g_hist[ei[N_EDGES + i]], 1);
        g_eperm[pos] = i;
    }
}

// =====================================================================
// pre-permute edge data into sorted order (once per call)
// =====================================================================
__global__ __launch_bounds__(256) void k_permute_ea(const float* __restrict__ EA) {
    size_t i = (size_t)blockIdx.x * blockDim.x + threadIdx.x;
    if (i >= (size_t)N_EDGES * NG) return;
    int e = (int)(i / NG);
    int k = (int)(i - (size_t)e * NG);
    int id = g_eperm[e];
    g_EAs[i] = EA[(size_t)id * NG + k];
}

__global__ void k_permute_meta(const int* __restrict__ ei, const float* __restrict__ ew) {
    int e = blockIdx.x * blockDim.x + threadIdx.x;
    if (e >= N_EDGES) return;
    int id = g_eperm[e];
    g_Cs[e] = 0.5f * (cospif(ew[id] * 0.125f) + 1.f);
    g_srcs[e] = ei[id];
    g_dsts[e] = ei[N_EDGES + id];
}

// =====================================================================
// pre FC: out = relu(x @ pre_W.T + pre_b)
// =====================================================================
__global__ __launch_bounds__(256) void k_pre(const float* __restrict__ x,
                                             const float* __restrict__ W,
                                             const float* __restrict__ b) {
    __shared__ float sW[64 * 93];
    int tid = threadIdx.x;
    for (int i = tid; i < 64 * 92; i += 256) {
        int f = i / 92, k = i % 92;
        sW[f * 93 + k] = W[i];
    }
    __syncthreads();
    int lane = tid & 31;
    int warp = (blockIdx.x * blockDim.x + tid) >> 5;
    int nwarps = (gridDim.x * blockDim.x) >> 5;
    float b0 = b[lane], b1 = b[lane + 32];
    for (int n = warp; n < N_NODES; n += nwarps) {
        const float* xr = x + (size_t)n * NF;
        float x0 = xr[lane];
        float x1 = xr[32 + lane];
        float x2 = (lane < 28) ? xr[64 + lane] : 0.f;
        float a0 = b0, a1 = b1;
#pragma unroll
        for (int k = 0; k < NF; k++) {
            float src = (k < 32) ? x0 : ((k < 64) ? x1 : x2);
            float xv = __shfl_sync(0xffffffffu, src, k & 31);
            a0 = fmaf(xv, sW[lane * 93 + k], a0);
            a1 = fmaf(xv, sW[(lane + 32) * 93 + k], a1);
        }
        g_out[(size_t)n * D1 + lane] = fmaxf(a0, 0.f);
        g_out[(size_t)n * D1 + lane + 32] = fmaxf(a1, 0.f);
    }
}

// =====================================================================
// lin1: g_h = g_out @ cf_W1.T
// =====================================================================
#define LIN1_SMEM ((4096 + 16384) * 4)
__global__ __launch_bounds__(256, 2) void k_lin1(const float* __restrict__ W) {
    extern __shared__ float sm[];
    float* sWt = sm;
    float* sA = sm + 4096;

    int tid = threadIdx.x;
    int tx = tid & 15, ty = tid >> 4;
    int n0 = blockIdx.x * 128;

    for (int i = tid; i < 64 * 64; i += 256) {
        int f = i >> 6, k = i & 63;
        sWt[k * 64 + f] = W[i];
    }
    for (int i = tid; i < 128 * 64; i += 256) {
        int e = i >> 6, k = i & 63;
        int n = n0 + e;
        float v = (n < N_NODES) ? g_out[n * D1 + k] : 0.f;
        *(float2*)&sA[e * 128 + 2 * k] = make_float2(v, v);
    }
    __syncthreads();

    ull acc[8][2];
#pragma unroll
    for (int ii = 0; ii < 8; ii++) { acc[ii][0] = 0ull; acc[ii][1] = 0ull; }
#pragma unroll
    for (int p = 0; p < 32; p++) {
        ulonglong2 b0 = *reinterpret_cast<const ulonglong2*>(&sWt[(2 * p) * 64 + 4 * tx]);
        ulonglong2 b1 = *reinterpret_cast<const ulonglong2*>(&sWt[(2 * p + 1) * 64 + 4 * tx]);
#pragma unroll
        for (int ii = 0; ii < 8; ii++) {
            ulonglong2 a = *reinterpret_cast<const ulonglong2*>(&sA[(ty + 16 * ii) * 128 + 4 * p]);
            acc[ii][0] = ffma2(a.x, b0.x, acc[ii][0]);
            acc[ii][1] = ffma2(a.x, b0.y, acc[ii][1]);
            acc[ii][0] = ffma2(a.y, b1.x, acc[ii][0]);
            acc[ii][1] = ffma2(a.y, b1.y, acc[ii][1]);
        }
    }
#pragma unroll
    for (int ii = 0; ii < 8; ii++) {
        int n = n0 + ty + 16 * ii;
        if (n < N_NODES) {
            float4 o;
            o.x = f2lo(acc[ii][0]); o.y = f2hi(acc[ii][0]);
            o.z = f2lo(acc[ii][1]); o.w = f2hi(acc[ii][1]);
            *(float4*)&g_h[n * D1 + 4 * tx] = o;
        }
    }
}

// =====================================================================
// k_edge v3: fully coalesced (pre-sorted inputs) + edge-pair f32x2 tiling
//            + run-compressed red.v4 scatter
// =====================================================================
#define EDGE_SMEM_WORDS 23552
#define EDGE_SMEM (EDGE_SMEM_WORDS * 4)
__global__ __launch_bounds__(256, 2) void k_edge(const float* __restrict__ W1,
                                                 const float* __restrict__ bias1,
                                                 const float* __restrict__ W2,
                                                 const float* __restrict__ bias2) {
    extern __shared__ float sm[];
    float* sW1A = sm;             // [50][64]  dup feats {4tx,4tx+1}
    float* sW1B = sm + 3200;      // [50][64]  dup feats {4tx+2,4tx+3}
    float* sW2A = sm + 6400;      // [64][64]
    float* sW2B = sm + 10496;     // [64][64]
    float* sAT  = sm + 14592;     // [64][132]: phase1 EA^T rows 0..49; phase2 hidden^T swizzled
    float* sB1  = sm + 23040;
    float* sB2  = sm + 23104;
    float* sC   = sm + 23168;     // 128
    int*   sSrc = (int*)(sm + 23296);
    int*   sDst = sSrc + 128;

    int tid = threadIdx.x;
    int tx = tid & 15, ty = tid >> 4;
    int e0 = blockIdx.x * 128;

    // weights, dup-chunked so B-operand LDS.128 lanes are 16B-consecutive
    for (int i = tid; i < 3200; i += 256) {
        int f = i / 50, k = i - f * 50;
        float v = W1[i];
        int j = f & 3;
        float* base = (j < 2) ? sW1A : sW1B;
        *(float2*)&base[k * 64 + (f >> 2) * 4 + (j & 1) * 2] = make_float2(v, v);
    }
    for (int i = tid; i < 4096; i += 256) {
        int f = i >> 6, k = i & 63;
        float v = W2[i];
        int j = f & 3;
        float* base = (j < 2) ? sW2A : sW2B;
        *(float2*)&base[k * 64 + (f >> 2) * 4 + (j & 1) * 2] = make_float2(v, v);
    }
    if (tid < 64) { sB1[tid] = bias1[tid]; sB2[tid] = bias2[tid]; }
    if (tid >= 128) {
        int t = tid - 128;
        sC[t] = g_Cs[e0 + t];
        sSrc[t] = g_srcs[e0 + t];
        sDst[t] = g_dsts[e0 + t];
    }
    // EA staging: contiguous coalesced read, transposed smem store
    {
        const float* blockEA = g_EAs + (size_t)e0 * NG;
        for (int i = tid; i < 128 * NG; i += 256) {
            int e = i / NG, k = i - e * NG;
            sAT[k * 132 + e] = blockEA[i];
        }
    }
    __syncthreads();

    // ---- phase 1: hidden = EA @ W1.T, K=50 ----
    ull acc[4][4];
#pragma unroll
    for (int p = 0; p < 4; p++)
#pragma unroll
        for (int j = 0; j < 4; j++) acc[p][j] = 0ull;

#pragma unroll 10
    for (int k = 0; k < 50; k++) {
        ulonglong2 a01 = *(const ulonglong2*)&sAT[k * 132 + 8 * ty];
        ulonglong2 a23 = *(const ulonglong2*)&sAT[k * 132 + 8 * ty + 4];
        ulonglong2 bA = *(const ulonglong2*)&sW1A[k * 64 + 4 * tx];
        ulonglong2 bB = *(const ulonglong2*)&sW1B[k * 64 + 4 * tx];
        acc[0][0] = ffma2(a01.x, bA.x, acc[0][0]);
        acc[0][1] = ffma2(a01.x, bA.y, acc[0][1]);
        acc[0][2] = ffma2(a01.x, bB.x, acc[0][2]);
        acc[0][3] = ffma2(a01.x, bB.y, acc[0][3]);
        acc[1][0] = ffma2(a01.y, bA.x, acc[1][0]);
        acc[1][1] = ffma2(a01.y, bA.y, acc[1][1]);
        acc[1][2] = ffma2(a01.y, bB.x, acc[1][2]);
        acc[1][3] = ffma2(a01.y, bB.y, acc[1][3]);
        acc[2][0] = ffma2(a23.x, bA.x, acc[2][0]);
        acc[2][1] = ffma2(a23.x, bA.y, acc[2][1]);
        acc[2][2] = ffma2(a23.x, bB.x, acc[2][2]);
        acc[2][3] = ffma2(a23.x, bB.y, acc[2][3]);
        acc[3][0] = ffma2(a23.y, bA.x, acc[3][0]);
        acc[3][1] = ffma2(a23.y, bA.y, acc[3][1]);
        acc[3][2] = ffma2(a23.y, bB.x, acc[3][2]);
        acc[3][3] = ffma2(a23.y, bB.y, acc[3][3]);
    }
    __syncthreads();

    // ssp + bias, store hidden transposed with XOR swizzle on 16B groups
#pragma unroll
    for (int j = 0; j < 4; j++) {
        int f = 4 * tx + j;
        float bj = sB1[f];
        int fx = f & 31;
#pragma unroll
        for (int p = 0; p < 4; p++) {
            float lo = sspf(f2lo(acc[p][j]) + bj);
            float hi = sspf(f2hi(acc[p][j]) + bj);
            int g = (2 * ty + (p >> 1)) ^ fx;
            *(float2*)&sAT[f * 132 + 4 * g + 2 * (p & 1)] = make_float2(lo, hi);
        }
    }
    __syncthreads();

    // ---- phase 2: w = hidden @ W2.T, K=64 ----
    ull wacc[4][4];
#pragma unroll
    for (int p = 0; p < 4; p++)
#pragma unroll
        for (int j = 0; j < 4; j++) wacc[p][j] = 0ull;

#pragma unroll 8
    for (int k = 0; k < 64; k++) {
        int kx = k & 31;
        ulonglong2 a01 = *(const ulonglong2*)&sAT[k * 132 + 4 * ((2 * ty) ^ kx)];
        ulonglong2 a23 = *(const ulonglong2*)&sAT[k * 132 + 4 * ((2 * ty + 1) ^ kx)];
        ulonglong2 bA = *(const ulonglong2*)&sW2A[k * 64 + 4 * tx];
        ulonglong2 bB = *(const ulonglong2*)&sW2B[k * 64 + 4 * tx];
        wacc[0][0] = ffma2(a01.x, bA.x, wacc[0][0]);
        wacc[0][1] = ffma2(a01.x, bA.y, wacc[0][1]);
        wacc[0][2] = ffma2(a01.x, bB.x, wacc[0][2]);
        wacc[0][3] = ffma2(a01.x, bB.y, wacc[0][3]);
        wacc[1][0] = ffma2(a01.y, bA.x, wacc[1][0]);
        wacc[1][1] = ffma2(a01.y, bA.y, wacc[1][1]);
        wacc[1][2] = ffma2(a01.y, bB.x, wacc[1][2]);
        wacc[1][3] = ffma2(a01.y, bB.y, wacc[1][3]);
        wacc[2][0] = ffma2(a23.x, bA.x, wacc[2][0]);
        wacc[2][1] = ffma2(a23.x, bA.y, wacc[2][1]);
        wacc[2][2] = ffma2(a23.x, bB.x, wacc[2][2]);
        wacc[2][3] = ffma2(a23.x, bB.y, wacc[2][3]);
        wacc[3][0] = ffma2(a23.y, bA.x, wacc[3][0]);
        wacc[3][1] = ffma2(a23.y, bA.y, wacc[3][1]);
        wacc[3][2] = ffma2(a23.y, bB.x, wacc[3][2]);
        wacc[3][3] = ffma2(a23.y, bB.y, wacc[3][3]);
    }

    // ---- phase 3: bias+cutoff+gather+run-compressed vectorized scatter ----
    float cb0 = sB2[4 * tx + 0], cb1 = sB2[4 * tx + 1];
    float cb2 = sB2[4 * tx + 2], cb3 = sB2[4 * tx + 3];
    int cur = -1;
    float4 racc = make_float4(0.f, 0.f, 0.f, 0.f);
#pragma unroll
    for (int ii = 0; ii < 8; ii++) {
        int p = ii >> 1, h = ii & 1;
        float w0 = (h ? f2hi(wacc[p][0]) : f2lo(wacc[p][0])) + cb0;
        float w1 = (h ? f2hi(wacc[p][1]) : f2lo(wacc[p][1])) + cb1;
        float w2 = (h ? f2hi(wacc[p][2]) : f2lo(wacc[p][2])) + cb2;
        float w3 = (h ? f2hi(wacc[p][3]) : f2lo(wacc[p][3])) + cb3;
        int e = 8 * ty + ii;
        float cc = sC[e];
        int sn = sSrc[e], dn = sDst[e];
        float4 hh = *(const float4*)&g_h[(size_t)sn * D1 + 4 * tx];
        float4 m = make_float4(w0 * cc * hh.x, w1 * cc * hh.y,
                               w2 * cc * hh.z, w3 * cc * hh.w);
        if (ii == 0) {
            cur = dn; racc = m;
        } else if (dn == cur) {
            racc.x += m.x; racc.y += m.y; racc.z += m.z; racc.w += m.w;
        } else {
            red4(&g_agg[(size_t)cur * D1 + 4 * tx], racc);
            cur = dn; racc = m;
        }
    }
    red4(&g_agg[(size_t)cur * D1 + 4 * tx], racc);
}

// =====================================================================
// node kernel
// =====================================================================
#define NODE_SMEM ((4096 + 4096 + 16384 + 64 + 64 + 64 + 64) * 4)
__global__ __launch_bounds__(256, 2) void k_node(const float* __restrict__ Wa,
                                                 const float* __restrict__ ba,
                                                 const float* __restrict__ Wb,
                                                 const float* __restrict__ bb) {
    extern __shared__ float sm[];
    float* sWat = sm;
    float* sWbt = sm + 4096;
    float* sA = sm + 8192;
    float* sBa = sm + 24576;
    float* sBb = sBa + 64;
    float* sSum = sBb + 64;
    float* sSq = sSum + 64;

    int tid = threadIdx.x;
    int tx = tid & 15, ty = tid >> 4;
    int n0 = blockIdx.x * 128;

    for (int i = tid; i < 64 * 64; i += 256) {
        int f = i >> 6, k = i & 63;
        sWat[k * 64 + f] = Wa[i];
        sWbt[k * 64 + f] = Wb[i];
    }
    if (tid < 64) { sBa[tid] = ba[tid]; sBb[tid] = bb[tid]; sSum[tid] = 0.f; sSq[tid] = 0.f; }
    for (int i = tid; i < 128 * 64; i += 256) {
        int e = i >> 6, k = i & 63;
        int n = n0 + e;
        float v = (n < N_NODES) ? g_agg[n * D1 + k] : 0.f;
        *(float2*)&sA[e * 128 + 2 * k] = make_float2(v, v);
    }
    __syncthreads();

    ull acc[8][2];
#pragma unroll
    for (int ii = 0; ii < 8; ii++) { acc[ii][0] = 0ull; acc[ii][1] = 0ull; }
#pragma unroll
    for (int p = 0; p < 32; p++) {
        ulonglong2 b0 = *reinterpret_cast<const ulonglong2*>(&sWat[(2 * p) * 64 + 4 * tx]);
        ulonglong2 b1 = *reinterpret_cast<const ulonglong2*>(&sWat[(2 * p + 1) * 64 + 4 * tx]);
#pragma unroll
        for (int ii = 0; ii < 8; ii++) {
            ulonglong2 a = *reinterpret_cast<const ulonglong2*>(&sA[(ty + 16 * ii) * 128 + 4 * p]);
            acc[ii][0] = ffma2(a.x, b0.x, acc[ii][0]);
            acc[ii][1] = ffma2(a.x, b0.y, acc[ii][1]);
            acc[ii][0] = ffma2(a.y, b1.x, acc[ii][0]);
            acc[ii][1] = ffma2(a.y, b1.y, acc[ii][1]);
        }
    }
    __syncthreads();

    float bb0 = sBa[4 * tx + 0], bb1 = sBa[4 * tx + 1];
    float bb2 = sBa[4 * tx + 2], bb3 = sBa[4 * tx + 3];
#pragma unroll
    for (int ii = 0; ii < 8; ii++) {
        int e = ty + 16 * ii;
        float h0 = sspf(f2lo(acc[ii][0]) + bb0);
        float h1 = sspf(f2hi(acc[ii][0]) + bb1);
        float h2 = sspf(f2lo(acc[ii][1]) + bb2);
        float h3 = sspf(f2hi(acc[ii][1]) + bb3);
        float2* p = (float2*)&sA[e * 128 + 8 * tx];
        p[0] = make_float2(h0, h0);
        p[1] = make_float2(h1, h1);
        p[2] = make_float2(h2, h2);
        p[3] = make_float2(h3, h3);
    }
    __syncthreads();

    ull wacc[8][2];
#pragma unroll
    for (int ii = 0; ii < 8; ii++) { wacc[ii][0] = 0ull; wacc[ii][1] = 0ull; }
#pragma unroll
    for (int p = 0; p < 32; p++) {
        ulonglong2 b0 = *reinterpret_cast<const ulonglong2*>(&sWbt[(2 * p) * 64 + 4 * tx]);
        ulonglong2 b1 = *reinterpret_cast<const ulonglong2*>(&sWbt[(2 * p + 1) * 64 + 4 * tx]);
#pragma unroll
        for (int ii = 0; ii < 8; ii++) {
            ulonglong2 a = *reinterpret_cast<const ulonglong2*>(&sA[(ty + 16 * ii) * 128 + 4 * p]);
            wacc[ii][0] = ffma2(a.x, b0.x, wacc[ii][0]);
            wacc[ii][1] = ffma2(a.x, b0.y, wacc[ii][1]);
            wacc[ii][0] = ffma2(a.y, b1.x, wacc[ii][0]);
            wacc[ii][1] = ffma2(a.y, b1.y, wacc[ii][1]);
        }
    }

    float c0 = sBb[4 * tx + 0], c1 = sBb[4 * tx + 1];
    float c2 = sBb[4 * tx + 2], c3 = sBb[4 * tx + 3];
    float ps0 = 0.f, ps1 = 0.f, ps2 = 0.f, ps3 = 0.f;
    float pq0 = 0.f, pq1 = 0.f, pq2 = 0.f, pq3 = 0.f;
#pragma unroll
    for (int ii = 0; ii < 8; ii++) {
        int n = n0 + ty + 16 * ii;
        if (n < N_NODES) {
            float4 prev = *(const float4*)&g_out[n * D1 + 4 * tx];
            float r0 = f2lo(wacc[ii][0]) + c0 + prev.x;
            float r1 = f2hi(wacc[ii][0]) + c1 + prev.y;
            float r2 = f2lo(wacc[ii][1]) + c2 + prev.z;
            float r3 = f2hi(wacc[ii][1]) + c3 + prev.w;
            float4 o; o.x = r0; o.y = r1; o.z = r2; o.w = r3;
            *(float4*)&g_out[n * D1 + 4 * tx] = o;
            ps0 += r0; ps1 += r1; ps2 += r2; ps3 += r3;
            pq0 += r0 * r0; pq1 += r1 * r1; pq2 += r2 * r2; pq3 += r3 * r3;
        }
    }
    atomicAdd(&sSum[4 * tx + 0], ps0); atomicAdd(&sSum[4 * tx + 1], ps1);
    atomicAdd(&sSum[4 * tx + 2], ps2); atomicAdd(&sSum[4 * tx + 3], ps3);
    atomicAdd(&sSq[4 * tx + 0], pq0);  atomicAdd(&sSq[4 * tx + 1], pq1);
    atomicAdd(&sSq[4 * tx + 2], pq2);  atomicAdd(&sSq[4 * tx + 3], pq3);
    __syncthreads();
    if (tid < 64) {
        atomicAdd(&g_bnstats[tid], sSum[tid]);
        atomicAdd(&g_bnstats[64 + tid], sSq[tid]);
    }
}

__global__ void k_bn(const float* __restrict__ g, const float* __restrict__ b) {
    int idx = blockIdx.x * blockDim.x + threadIdx.x;
    if (idx >= N_NODES * D1) return;
    int f = idx & 63;
    const float invN = 1.f / (float)N_NODES;
    float mu = g_bnstats[f] * invN;
    float var = fmaxf(g_bnstats[64 + f] * invN - mu * mu, 0.f);
    float sc = rsqrtf(var + BN_EPS) * g[f];
    g_out[idx] = (g_out[idx] - mu) * sc + b[f];
}

__global__ void k_pool(const int* __restrict__ batch) {
    int idx = blockIdx.x * blockDim.x + threadIdx.x;
    if (idx >= N_NODES * D1) return;
    int n = idx >> 6, f = idx & 63;
    int bg = batch[n];
    atomicAdd(&g_pool[bg * D1 + f], g_out[idx]);
    if (f == 0) atomicAdd(&g_cnt[bg], 1.f);
}

__global__ void k_head(const float* __restrict__ postW, const float* __restrict__ postb,
                       const float* __restrict__ outW, const float* __restrict__ outb,
                       float* __restrict__ y) {
    int g = blockIdx.x;
    int f = threadIdx.x;
    __shared__ float sp[64];
    __shared__ float sr[2];
    float cnt = fmaxf(g_cnt[g], 1.f);
    sp[f] = g_pool[g * D1 + f] / cnt;
    __syncthreads();
    float a = postb[f];
#pragma unroll
    for (int k = 0; k < 64; k++) a = fmaf(sp[k], postW[f * 64 + k], a);
    float hp = fmaxf(a, 0.f) * outW[f];
#pragma unroll
    for (int o = 16; o > 0; o >>= 1) hp += __shfl_down_sync(0xffffffffu, hp, o);
    if ((f & 31) == 0) sr[f >> 5] = hp;
    __syncthreads();
    if (f == 0) y[g] = sr[0] + sr[1] + outb[0];
}

// =====================================================================
extern "C" void kernel_launch(void* const* d_in, const int* in_sizes, int n_in,
                              void* d_out, int out_size) {
    const float* x      = (const float*)d_in[0];
    const float* ew     = (const float*)d_in[1];
    const float* ea     = (const float*)d_in[2];
    const int*   ei     = (const int*)d_in[3];
    const int*   batch  = (const int*)d_in[4];
    const float* pre_W  = (const float*)d_in[5];
    const float* pre_b  = (const float*)d_in[6];
    const float* mlp_W1 = (const float*)d_in[7];
    const float* mlp_b1 = (const float*)d_in[8];
    const float* mlp_W2 = (const float*)d_in[9];
    const float* mlp_b2 = (const float*)d_in[10];
    const float* cf_W1  = (const float*)d_in[11];
    const float* cf_W2  = (const float*)d_in[12];
    const float* cf_b2  = (const float*)d_in[13];
    const float* int_W  = (const float*)d_in[14];
    const float* int_b  = (const float*)d_in[15];
    const float* bn_g   = (const float*)d_in[16];
    const float* bn_b   = (const float*)d_in[17];
    const float* post_W = (const float*)d_in[18];
    const float* post_b = (const float*)d_in[19];
    const float* out_W  = (const float*)d_in[20];
    const float* out_b  = (const float*)d_in[21];
    float* y = (float*)d_out;

    void *agg_p, *bn_p, *pool_p, *cnt_p, *hist_p;
    cudaGetSymbolAddress(&agg_p, g_agg);
    cudaGetSymbolAddress(&bn_p, g_bnstats);
    cudaGetSymbolAddress(&pool_p, g_pool);
    cudaGetSymbolAddress(&cnt_p, g_cnt);
    cudaGetSymbolAddress(&hist_p, g_hist);

    cudaFuncSetAttribute(k_edge, cudaFuncAttributeMaxDynamicSharedMemorySize, EDGE_SMEM);
    cudaFuncSetAttribute(k_node, cudaFuncAttributeMaxDynamicSharedMemorySize, NODE_SMEM);
    cudaFuncSetAttribute(k_lin1, cudaFuncAttributeMaxDynamicSharedMemorySize, LIN1_SMEM);

    // counting sort of edges by dst + materialize sorted edge data
    cudaMemsetAsync(hist_p, 0, N_NODES * sizeof(int));
    k_hist<<<(N_EDGES + 255) / 256, 256>>>(ei);
    k_scan<<<1, 1024>>>();
    k_scatter<<<(N_EDGES + 255) / 256, 256>>>(ei);
    {
        size_t tot = (size_t)N_EDGES * NG;
        k_permute_ea<<<(unsigned)((tot + 255) / 256), 256>>>(ea);
        k_permute_meta<<<(N_EDGES + 255) / 256, 256>>>(ei, ew);
    }

    k_pre<<<512, 256>>>(x, pre_W, pre_b);
    cudaMemsetAsync(pool_p, 0, N_GRAPHS * D1 * sizeof(float));
    cudaMemsetAsync(cnt_p, 0, N_GRAPHS * sizeof(float));

    for (int l = 0; l < 3; l++) {
        k_lin1<<<(N_NODES + 127) / 128, 256, LIN1_SMEM>>>(cf_W1 + l * 64 * 64);
        cudaMemsetAsync(agg_p, 0, (size_t)N_NODES * D1 * sizeof(float));
        cudaMemsetAsync(bn_p, 0, 2 * D1 * sizeof(float));
        k_edge<<<N_EDGES / 128, 256, EDGE_SMEM>>>(mlp_W1 + l * 64 * 50, mlp_b1 + l * 64,
                                                  mlp_W2 + l * 64 * 64, mlp_b2 + l * 64);
        k_node<<<(N_NODES + 127) / 128, 256, NODE_SMEM>>>(cf_W2 + l * 64 * 64, cf_b2 + l * 64,
                                                          int_W + l * 64 * 64, int_b + l * 64);
        k_bn<<<(N_NODES * D1 + 255) / 256, 256>>>(bn_g + l * 64, bn_b + l * 64);
    }

    k_pool<<<(N_NODES * D1 + 255) / 256, 256>>>(batch);
    k_head<<<N_GRAPHS, 64>>>(post_W, post_b, out_W, out_b, y);
}

// round 4
// speedup vs baseline: 1.1908x; 1.1908x over previous
#include <cuda_runtime.h>
#include <math_constants.h>

#define N_NODES 50000
#define N_EDGES 1200000
#define N_GRAPHS 512
#define D1 64
#define NF 92
#define NG 50
#define BN_EPS 1e-5f
#define LOG2F_C 0.6931471805599453f

#define N_TILES (N_EDGES / 128)   // 9375
#define EDGE_GRID 304

typedef unsigned long long ull;

// -------------------- device scratch --------------------
__device__ float g_out[N_NODES * D1];
__device__ float g_h[N_NODES * D1];
__device__ float g_agg[N_NODES * D1];
__device__ float g_bnstats[2 * D1];
__device__ float g_pool[N_GRAPHS * D1];
__device__ float g_cnt[N_GRAPHS];
__device__ int   g_hist[N_NODES];
__device__ int   g_eperm[N_EDGES];
__device__ float g_Cs[N_EDGES];
__device__ int   g_srcs[N_EDGES];
__device__ int   g_dsts[N_EDGES];

// -------------------- helpers --------------------
__device__ __forceinline__ ull ffma2(ull a, ull b, ull c) {
    ull d;
    asm("fma.rn.f32x2 %0, %1, %2, %3;" : "=l"(d) : "l"(a), "l"(b), "l"(c));
    return d;
}
__device__ __forceinline__ ull dup2(float v) {
    ull r;
    asm("mov.b64 %0, {%1, %1};" : "=l"(r) : "f"(v));
    return r;
}
__device__ __forceinline__ float f2lo(ull v) { return __uint_as_float((unsigned)(v & 0xffffffffull)); }
__device__ __forceinline__ float f2hi(ull v) { return __uint_as_float((unsigned)(v >> 32)); }

__device__ __forceinline__ float sspf(float v) {
    return fmaxf(v, 0.f) + __logf(1.f + __expf(-fabsf(v))) - LOG2F_C;
}

__device__ __forceinline__ void red4(float* p, float4 v) {
    asm volatile("red.global.add.v4.f32 [%0], {%1,%2,%3,%4};"
                 :: "l"(p), "f"(v.x), "f"(v.y), "f"(v.z), "f"(v.w) : "memory");
}

__device__ __forceinline__ void cp8(unsigned dst, const void* src) {
    asm volatile("cp.async.ca.shared.global [%0], [%1], 8;" :: "r"(dst), "l"(src));
}
__device__ __forceinline__ void cp_commit() {
    asm volatile("cp.async.commit_group;" ::: "memory");
}
__device__ __forceinline__ void cp_wait0() {
    asm volatile("cp.async.wait_group 0;" ::: "memory");
}

// =====================================================================
// counting sort by dst
// =====================================================================
__global__ void k_hist(const int* __restrict__ ei) {
    int i = blockIdx.x * blockDim.x + threadIdx.x;
    if (i < N_EDGES) atomicAdd(&g_hist[ei[N_EDGES + i]], 1);
}

__global__ __launch_bounds__(1024) void k_scan() {
    __shared__ int ss[1024];
    int t = threadIdx.x;
    int lo = t * 49;
    int hi = min(lo + 49, N_NODES);
    int s = 0;
    for (int b = lo; b < hi; b++) s += g_hist[b];
    ss[t] = s;
    __syncthreads();
    for (int off = 1; off < 1024; off <<= 1) {
        int v = (t >= off) ? ss[t - off] : 0;
        __syncthreads();
        ss[t] += v;
        __syncthreads();
    }
    int run = ss[t] - s;
    for (int b = lo; b < hi; b++) {
        int c = g_hist[b];
        g_hist[b] = run;
        run += c;
    }
}

__global__ void k_scatter(const int* __restrict__ ei) {
    int i = blockIdx.x * blockDim.x + threadIdx.x;
    if (i < N_EDGES) {
        int pos = atomicAdd(&g_hist[ei[N_EDGES + i]], 1);
        g_eperm[pos] = i;
    }
}

__global__ void k_permute_meta(const int* __restrict__ ei, const float* __restrict__ ew) {
    int e = blockIdx.x * blockDim.x + threadIdx.x;
    if (e >= N_EDGES) return;
    int id = g_eperm[e];
    g_Cs[e] = 0.5f * (cospif(ew[id] * 0.125f) + 1.f);
    g_srcs[e] = ei[id];
    g_dsts[e] = ei[N_EDGES + e >= 0 ? N_EDGES + id : 0];
}

// =====================================================================
// pre FC: out = relu(x @ pre_W.T + pre_b)
// =====================================================================
__global__ __launch_bounds__(256) void k_pre(const float* __restrict__ x,
                                             const float* __restrict__ W,
                                             const float* __restrict__ b) {
    __shared__ float sW[64 * 93];
    int tid = threadIdx.x;
    for (int i = tid; i < 64 * 92; i += 256) {
        int f = i / 92, k = i % 92;
        sW[f * 93 + k] = W[i];
    }
    __syncthreads();
    int lane = tid & 31;
    int warp = (blockIdx.x * blockDim.x + tid) >> 5;
    int nwarps = (gridDim.x * blockDim.x) >> 5;
    float b0 = b[lane], b1 = b[lane + 32];
    for (int n = warp; n < N_NODES; n += nwarps) {
        const float* xr = x + (size_t)n * NF;
        float x0 = xr[lane];
        float x1 = xr[32 + lane];
        float x2 = (lane < 28) ? xr[64 + lane] : 0.f;
        float a0 = b0, a1 = b1;
#pragma unroll
        for (int k = 0; k < NF; k++) {
            float src = (k < 32) ? x0 : ((k < 64) ? x1 : x2);
            float xv = __shfl_sync(0xffffffffu, src, k & 31);
            a0 = fmaf(xv, sW[lane * 93 + k], a0);
            a1 = fmaf(xv, sW[(lane + 32) * 93 + k], a1);
        }
        g_out[(size_t)n * D1 + lane] = fmaxf(a0, 0.f);
        g_out[(size_t)n * D1 + lane + 32] = fmaxf(a1, 0.f);
    }
}

// =====================================================================
// lin1: g_h = g_out @ cf_W1.T
// =====================================================================
#define LIN1_SMEM ((4096 + 16384) * 4)
__global__ __launch_bounds__(256, 2) void k_lin1(const float* __restrict__ W) {
    extern __shared__ float sm[];
    float* sWt = sm;
    float* sA = sm + 4096;

    int tid = threadIdx.x;
    int tx = tid & 15, ty = tid >> 4;
    int n0 = blockIdx.x * 128;

    for (int i = tid; i < 64 * 64; i += 256) {
        int f = i >> 6, k = i & 63;
        sWt[k * 64 + f] = W[i];
    }
    for (int i = tid; i < 128 * 64; i += 256) {
        int e = i >> 6, k = i & 63;
        int n = n0 + e;
        float v = (n < N_NODES) ? g_out[n * D1 + k] : 0.f;
        *(float2*)&sA[e * 128 + 2 * k] = make_float2(v, v);
    }
    __syncthreads();

    ull acc[8][2];
#pragma unroll
    for (int ii = 0; ii < 8; ii++) { acc[ii][0] = 0ull; acc[ii][1] = 0ull; }
#pragma unroll
    for (int p = 0; p < 32; p++) {
        ulonglong2 b0 = *reinterpret_cast<const ulonglong2*>(&sWt[(2 * p) * 64 + 4 * tx]);
        ulonglong2 b1 = *reinterpret_cast<const ulonglong2*>(&sWt[(2 * p + 1) * 64 + 4 * tx]);
#pragma unroll
        for (int ii = 0; ii < 8; ii++) {
            ulonglong2 a = *reinterpret_cast<const ulonglong2*>(&sA[(ty + 16 * ii) * 128 + 4 * p]);
            acc[ii][0] = ffma2(a.x, b0.x, acc[ii][0]);
            acc[ii][1] = ffma2(a.x, b0.y, acc[ii][1]);
            acc[ii][0] = ffma2(a.y, b1.x, acc[ii][0]);
            acc[ii][1] = ffma2(a.y, b1.y, acc[ii][1]);
        }
    }
#pragma unroll
    for (int ii = 0; ii < 8; ii++) {
        int n = n0 + ty + 16 * ii;
        if (n < N_NODES) {
            float4 o;
            o.x = f2lo(acc[ii][0]); o.y = f2hi(acc[ii][0]);
            o.z = f2lo(acc[ii][1]); o.w = f2hi(acc[ii][1]);
            *(float4*)&g_h[n * D1 + 4 * tx] = o;
        }
    }
}

// =====================================================================
// k_edge v4: persistent CTAs, weights staged once, cp.async prefetched
// EA gather (eperm indirection), feature-pair f32x2 accumulators,
// run-compressed red.v4 scatter.
//   thread (tx=tid&7, ty=tid>>3): feats 8tx..8tx+7, edges 4ty..4ty+3
// =====================================================================
// smem words: W1T 3200 | W2T 4096 | sEA 128*54=6912 | sHid 128*66=8448 | b1 64 | b2 64
#define EDGE_W1T   0
#define EDGE_W2T   3200
#define EDGE_EA    7296
#define EDGE_HID   14208
#define EDGE_B1    22656
#define EDGE_B2    22720
#define EDGE_SMEM_WORDS 22784
#define EDGE_SMEM (EDGE_SMEM_WORDS * 4)

__device__ __forceinline__ void issue_ea(const float* __restrict__ EA, int e0,
                                         unsigned sEA_u32, int tid) {
    int r = tid >> 1, half = tid & 1;
    int id = __ldg(&g_eperm[e0 + r]);
    const float* src = EA + (size_t)id * NG + (half ? 26 : 0);
    unsigned dst = sEA_u32 + (unsigned)(r * 54 + (half ? 26 : 0)) * 4u;
    int ng = half ? 12 : 13;
    for (int g = 0; g < ng; g++)
        cp8(dst + g * 8, src + g * 2);
}

__global__ __launch_bounds__(256, 2) void k_edge(const float* __restrict__ EA,
                                                 const float* __restrict__ W1,
                                                 const float* __restrict__ bias1,
                                                 const float* __restrict__ W2,
                                                 const float* __restrict__ bias2) {
    extern __shared__ float sm[];
    float* sW1T = sm + EDGE_W1T;   // [50][64]  (k-major, transposed)
    float* sW2T = sm + EDGE_W2T;   // [64][64]
    float* sEA  = sm + EDGE_EA;    // [128][54] row-major EA tile
    float* sHid = sm + EDGE_HID;   // [128][66] row-major hidden
    float* sB1  = sm + EDGE_B1;
    float* sB2  = sm + EDGE_B2;

    int tid = threadIdx.x;
    int tx = tid & 7, ty = tid >> 3;
    unsigned sEA_u32 = (unsigned)__cvta_generic_to_shared(sEA);

    // ---- stage weights once ----
    for (int i = tid; i < 3200; i += 256) {
        int f = i / 50, k = i - f * 50;
        sW1T[k * 64 + f] = W1[i];
    }
    for (int i = tid; i < 4096; i += 256) {
        int f = i >> 6, k = i & 63;
        sW2T[k * 64 + f] = W2[i];
    }
    if (tid < 64) { sB1[tid] = bias1[tid]; sB2[tid] = bias2[tid]; }

    int tile = blockIdx.x;
    if (tile < N_TILES) {
        issue_ea(EA, tile * 128, sEA_u32, tid);
    }
    cp_commit();

    // per-thread bias regs
    float b2r[8];
#pragma unroll
    for (int i = 0; i < 8; i++) b2r[i] = bias2[8 * tx + i];

    for (; tile < N_TILES; tile += EDGE_GRID) {
        int e0 = tile * 128;
        cp_wait0();
        __syncthreads();   // EA tile ready; sHid free; weights ready (first iter)

        // ---- phase 1: hidden = ssp(EA @ W1T + b1), K=50 ----
        ull acc[4][4];
#pragma unroll
        for (int j = 0; j < 4; j++)
#pragma unroll
            for (int p = 0; p < 4; p++) acc[j][p] = 0ull;

#pragma unroll 10
        for (int k = 0; k < 50; k++) {
            ulonglong2 bA = *(const ulonglong2*)&sW1T[k * 64 + 8 * tx];
            ulonglong2 bB = *(const ulonglong2*)&sW1T[k * 64 + 8 * tx + 4];
#pragma unroll
            for (int j = 0; j < 4; j++) {
                ull av = dup2(sEA[(4 * ty + j) * 54 + k]);
                acc[j][0] = ffma2(av, bA.x, acc[j][0]);
                acc[j][1] = ffma2(av, bA.y, acc[j][1]);
                acc[j][2] = ffma2(av, bB.x, acc[j][2]);
                acc[j][3] = ffma2(av, bB.y, acc[j][3]);
            }
        }
        __syncthreads();   // everyone done reading sEA

        // prefetch next tile's EA (overlaps hid store + phase2 + scatter)
        if (tile + EDGE_GRID < N_TILES) {
            issue_ea(EA, (tile + EDGE_GRID) * 128, sEA_u32, tid);
        }
        cp_commit();

        // ssp + bias -> sHid (row-major, stride 66)
#pragma unroll
        for (int j = 0; j < 4; j++) {
            int e = 4 * ty + j;
#pragma unroll
            for (int p = 0; p < 4; p++) {
                float lo = sspf(f2lo(acc[j][p]) + sB1[8 * tx + 2 * p]);
                float hi = sspf(f2hi(acc[j][p]) + sB1[8 * tx + 2 * p + 1]);
                *(float2*)&sHid[e * 66 + 8 * tx + 2 * p] = make_float2(lo, hi);
            }
        }
        __syncthreads();

        // ---- phase 2: w = hid @ W2T, K=64 ----
        ull wacc[4][4];
#pragma unroll
        for (int j = 0; j < 4; j++)
#pragma unroll
            for (int p = 0; p < 4; p++) wacc[j][p] = 0ull;

#pragma unroll 8
        for (int k = 0; k < 64; k++) {
            ulonglong2 bA = *(const ulonglong2*)&sW2T[k * 64 + 8 * tx];
            ulonglong2 bB = *(const ulonglong2*)&sW2T[k * 64 + 8 * tx + 4];
#pragma unroll
            for (int j = 0; j < 4; j++) {
                ull av = dup2(sHid[(4 * ty + j) * 66 + k]);
                wacc[j][0] = ffma2(av, bA.x, wacc[j][0]);
                wacc[j][1] = ffma2(av, bA.y, wacc[j][1]);
                wacc[j][2] = ffma2(av, bB.x, wacc[j][2]);
                wacc[j][3] = ffma2(av, bB.y, wacc[j][3]);
            }
        }

        // ---- phase 3: bias + cutoff + gather h[src] + run-compressed scatter ----
        int cur = -1;
        float4 r0 = make_float4(0.f, 0.f, 0.f, 0.f);
        float4 r1 = make_float4(0.f, 0.f, 0.f, 0.f);
#pragma unroll
        for (int j = 0; j < 4; j++) {
            int ge = e0 + 4 * ty + j;
            float cc = __ldg(&g_Cs[ge]);
            int sn = __ldg(&g_srcs[ge]);
            int dn = __ldg(&g_dsts[ge]);
            float4 h0 = *(const float4*)&g_h[(size_t)sn * D1 + 8 * tx];
            float4 h1 = *(const float4*)&g_h[(size_t)sn * D1 + 8 * tx + 4];
            float4 m0, m1;
            m0.x = (f2lo(wacc[j][0]) + b2r[0]) * cc * h0.x;
            m0.y = (f2hi(wacc[j][0]) + b2r[1]) * cc * h0.y;
            m0.z = (f2lo(wacc[j][1]) + b2r[2]) * cc * h0.z;
            m0.w = (f2hi(wacc[j][1]) + b2r[3]) * cc * h0.w;
            m1.x = (f2lo(wacc[j][2]) + b2r[4]) * cc * h1.x;
            m1.y = (f2hi(wacc[j][2]) + b2r[5]) * cc * h1.y;
            m1.z = (f2lo(wacc[j][3]) + b2r[6]) * cc * h1.z;
            m1.w = (f2hi(wacc[j][3]) + b2r[7]) * cc * h1.w;
            if (j == 0) {
                cur = dn; r0 = m0; r1 = m1;
            } else if (dn == cur) {
                r0.x += m0.x; r0.y += m0.y; r0.z += m0.z; r0.w += m0.w;
                r1.x += m1.x; r1.y += m1.y; r1.z += m1.z; r1.w += m1.w;
            } else {
                red4(&g_agg[(size_t)cur * D1 + 8 * tx], r0);
                red4(&g_agg[(size_t)cur * D1 + 8 * tx + 4], r1);
                cur = dn; r0 = m0; r1 = m1;
            }
        }
        red4(&g_agg[(size_t)cur * D1 + 8 * tx], r0);
        red4(&g_agg[(size_t)cur * D1 + 8 * tx + 4], r1);
    }
}

// =====================================================================
// node kernel
// =====================================================================
#define NODE_SMEM ((4096 + 4096 + 16384 + 64 + 64 + 64 + 64) * 4)
__global__ __launch_bounds__(256, 2) void k_node(const float* __restrict__ Wa,
                                                 const float* __restrict__ ba,
                                                 const float* __restrict__ Wb,
                                                 const float* __restrict__ bb) {
    extern __shared__ float sm[];
    float* sWat = sm;
    float* sWbt = sm + 4096;
    float* sA = sm + 8192;
    float* sBa = sm + 24576;
    float* sBb = sBa + 64;
    float* sSum = sBb + 64;
    float* sSq = sSum + 64;

    int tid = threadIdx.x;
    int tx = tid & 15, ty = tid >> 4;
    int n0 = blockIdx.x * 128;

    for (int i = tid; i < 64 * 64; i += 256) {
        int f = i >> 6, k = i & 63;
        sWat[k * 64 + f] = Wa[i];
        sWbt[k * 64 + f] = Wb[i];
    }
    if (tid < 64) { sBa[tid] = ba[tid]; sBb[tid] = bb[tid]; sSum[tid] = 0.f; sSq[tid] = 0.f; }
    for (int i = tid; i < 128 * 64; i += 256) {
        int e = i >> 6, k = i & 63;
        int n = n0 + e;
        float v = (n < N_NODES) ? g_agg[n * D1 + k] : 0.f;
        *(float2*)&sA[e * 128 + 2 * k] = make_float2(v, v);
    }
    __syncthreads();

    ull acc[8][2];
#pragma unroll
    for (int ii = 0; ii < 8; ii++) { acc[ii][0] = 0ull; acc[ii][1] = 0ull; }
#pragma unroll
    for (int p = 0; p < 32; p++) {
        ulonglong2 b0 = *reinterpret_cast<const ulonglong2*>(&sWat[(2 * p) * 64 + 4 * tx]);
        ulonglong2 b1 = *reinterpret_cast<const ulonglong2*>(&sWat[(2 * p + 1) * 64 + 4 * tx]);
#pragma unroll
        for (int ii = 0; ii < 8; ii++) {
            ulonglong2 a = *reinterpret_cast<const ulonglong2*>(&sA[(ty + 16 * ii) * 128 + 4 * p]);
            acc[ii][0] = ffma2(a.x, b0.x, acc[ii][0]);
            acc[ii][1] = ffma2(a.x, b0.y, acc[ii][1]);
            acc[ii][0] = ffma2(a.y, b1.x, acc[ii][0]);
            acc[ii][1] = ffma2(a.y, b1.y, acc[ii][1]);
        }
    }
    __syncthreads();

    float bb0 = sBa[4 * tx + 0], bb1 = sBa[4 * tx + 1];
    float bb2 = sBa[4 * tx + 2], bb3 = sBa[4 * tx + 3];
#pragma unroll
    for (int ii = 0; ii < 8; ii++) {
        int e = ty + 16 * ii;
        float h0 = sspf(f2lo(acc[ii][0]) + bb0);
        float h1 = sspf(f2hi(acc[ii][0]) + bb1);
        float h2 = sspf(f2lo(acc[ii][1]) + bb2);
        float h3 = sspf(f2hi(acc[ii][1]) + bb3);
        float2* p = (float2*)&sA[e * 128 + 8 * tx];
        p[0] = make_float2(h0, h0);
        p[1] = make_float2(h1, h1);
        p[2] = make_float2(h2, h2);
        p[3] = make_float2(h3, h3);
    }
    __syncthreads();

    ull wacc[8][2];
#pragma unroll
    for (int ii = 0; ii < 8; ii++) { wacc[ii][0] = 0ull; wacc[ii][1] = 0ull; }
#pragma unroll
    for (int p = 0; p < 32; p++) {
        ulonglong2 b0 = *reinterpret_cast<const ulonglong2*>(&sWbt[(2 * p) * 64 + 4 * tx]);
        ulonglong2 b1 = *reinterpret_cast<const ulonglong2*>(&sWbt[(2 * p + 1) * 64 + 4 * tx]);
#pragma unroll
        for (int ii = 0; ii < 8; ii++) {
            ulonglong2 a = *reinterpret_cast<const ulonglong2*>(&sA[(ty + 16 * ii) * 128 + 4 * p]);
            wacc[ii][0] = ffma2(a.x, b0.x, wacc[ii][0]);
            wacc[ii][1] = ffma2(a.x, b0.y, wacc[ii][1]);
            wacc[ii][0] = ffma2(a.y, b1.x, wacc[ii][0]);
            wacc[ii][1] = ffma2(a.y, b1.y, wacc[ii][1]);
        }
    }

    float c0 = sBb[4 * tx + 0], c1 = sBb[4 * tx + 1];
    float c2 = sBb[4 * tx + 2], c3 = sBb[4 * tx + 3];
    float ps0 = 0.f, ps1 = 0.f, ps2 = 0.f, ps3 = 0.f;
    float pq0 = 0.f, pq1 = 0.f, pq2 = 0.f, pq3 = 0.f;
#pragma unroll
    for (int ii = 0; ii < 8; ii++) {
        int n = n0 + ty + 16 * ii;
        if (n < N_NODES) {
            float4 prev = *(const float4*)&g_out[n * D1 + 4 * tx];
            float r0 = f2lo(wacc[ii][0]) + c0 + prev.x;
            float r1 = f2hi(wacc[ii][0]) + c1 + prev.y;
            float r2 = f2lo(wacc[ii][1]) + c2 + prev.z;
            float r3 = f2hi(wacc[ii][1]) + c3 + prev.w;
            float4 o; o.x = r0; o.y = r1; o.z = r2; o.w = r3;
            *(float4*)&g_out[n * D1 + 4 * tx] = o;
            ps0 += r0; ps1 += r1; ps2 += r2; ps3 += r3;
            pq0 += r0 * r0; pq1 += r1 * r1; pq2 += r2 * r2; pq3 += r3 * r3;
        }
    }
    atomicAdd(&sSum[4 * tx + 0], ps0); atomicAdd(&sSum[4 * tx + 1], ps1);
    atomicAdd(&sSum[4 * tx + 2], ps2); atomicAdd(&sSum[4 * tx + 3], ps3);
    atomicAdd(&sSq[4 * tx + 0], pq0);  atomicAdd(&sSq[4 * tx + 1], pq1);
    atomicAdd(&sSq[4 * tx + 2], pq2);  atomicAdd(&sSq[4 * tx + 3], pq3);
    __syncthreads();
    if (tid < 64) {
        atomicAdd(&g_bnstats[tid], sSum[tid]);
        atomicAdd(&g_bnstats[64 + tid], sSq[tid]);
    }
}

__global__ void k_bn(const float* __restrict__ g, const float* __restrict__ b) {
    int idx = blockIdx.x * blockDim.x + threadIdx.x;
    if (idx >= N_NODES * D1) return;
    int f = idx & 63;
    const float invN = 1.f / (float)N_NODES;
    float mu = g_bnstats[f] * invN;
    float var = fmaxf(g_bnstats[64 + f] * invN - mu * mu, 0.f);
    float sc = rsqrtf(var + BN_EPS) * g[f];
    g_out[idx] = (g_out[idx] - mu) * sc + b[f];
}

__global__ void k_pool(const int* __restrict__ batch) {
    int idx = blockIdx.x * blockDim.x + threadIdx.x;
    if (idx >= N_NODES * D1) return;
    int n = idx >> 6, f = idx & 63;
    int bg = batch[n];
    atomicAdd(&g_pool[bg * D1 + f], g_out[idx]);
    if (f == 0) atomicAdd(&g_cnt[bg], 1.f);
}

__global__ void k_head(const float* __restrict__ postW, const float* __restrict__ postb,
                       const float* __restrict__ outW, const float* __restrict__ outb,
                       float* __restrict__ y) {
    int g = blockIdx.x;
    int f = threadIdx.x;
    __shared__ float sp[64];
    __shared__ float sr[2];
    float cnt = fmaxf(g_cnt[g], 1.f);
    sp[f] = g_pool[g * D1 + f] / cnt;
    __syncthreads();
    float a = postb[f];
#pragma unroll
    for (int k = 0; k < 64; k++) a = fmaf(sp[k], postW[f * 64 + k], a);
    float hp = fmaxf(a, 0.f) * outW[f];
#pragma unroll
    for (int o = 16; o > 0; o >>= 1) hp += __shfl_down_sync(0xffffffffu, hp, o);
    if ((f & 31) == 0) sr[f >> 5] = hp;
    __syncthreads();
    if (f == 0) y[g] = sr[0] + sr[1] + outb[0];
}

// =====================================================================
extern "C" void kernel_launch(void* const* d_in, const int* in_sizes, int n_in,
                              void* d_out, int out_size) {
    const float* x      = (const float*)d_in[0];
    const float* ew     = (const float*)d_in[1];
    const float* ea     = (const float*)d_in[2];
    const int*   ei     = (const int*)d_in[3];
    const int*   batch  = (const int*)d_in[4];
    const float* pre_W  = (const float*)d_in[5];
    const float* pre_b  = (const float*)d_in[6];
    const float* mlp_W1 = (const float*)d_in[7];
    const float* mlp_b1 = (const float*)d_in[8];
    const float* mlp_W2 = (const float*)d_in[9];
    const float* mlp_b2 = (const float*)d_in[10];
    const float* cf_W1  = (const float*)d_in[11];
    const float* cf_W2  = (const float*)d_in[12];
    const float* cf_b2  = (const float*)d_in[13];
    const float* int_W  = (const float*)d_in[14];
    const float* int_b  = (const float*)d_in[15];
    const float* bn_g   = (const float*)d_in[16];
    const float* bn_b   = (const float*)d_in[17];
    const float* post_W = (const float*)d_in[18];
    const float* post_b = (const float*)d_in[19];
    const float* out_W  = (const float*)d_in[20];
    const float* out_b  = (const float*)d_in[21];
    float* y = (float*)d_out;

    void *agg_p, *bn_p, *pool_p, *cnt_p, *hist_p;
    cudaGetSymbolAddress(&agg_p, g_agg);
    cudaGetSymbolAddress(&bn_p, g_bnstats);
    cudaGetSymbolAddress(&pool_p, g_pool);
    cudaGetSymbolAddress(&cnt_p, g_cnt);
    cudaGetSymbolAddress(&hist_p, g_hist);

    cudaFuncSetAttribute(k_edge, cudaFuncAttributeMaxDynamicSharedMemorySize, EDGE_SMEM);
    cudaFuncSetAttribute(k_node, cudaFuncAttributeMaxDynamicSharedMemorySize, NODE_SMEM);
    cudaFuncSetAttribute(k_lin1, cudaFuncAttributeMaxDynamicSharedMemorySize, LIN1_SMEM);

    // counting sort of edges by dst + sorted meta
    cudaMemsetAsync(hist_p, 0, N_NODES * sizeof(int));
    k_hist<<<(N_EDGES + 255) / 256, 256>>>(ei);
    k_scan<<<1, 1024>>>();
    k_scatter<<<(N_EDGES + 255) / 256, 256>>>(ei);
    k_permute_meta<<<(N_EDGES + 255) / 256, 256>>>(ei, ew);

    k_pre<<<512, 256>>>(x, pre_W, pre_b);
    cudaMemsetAsync(pool_p, 0, N_GRAPHS * D1 * sizeof(float));
    cudaMemsetAsync(cnt_p, 0, N_GRAPHS * sizeof(float));

    for (int l = 0; l < 3; l++) {
        k_lin1<<<(N_NODES + 127) / 128, 256, LIN1_SMEM>>>(cf_W1 + l * 64 * 64);
        cudaMemsetAsync(agg_p, 0, (size_t)N_NODES * D1 * sizeof(float));
        cudaMemsetAsync(bn_p, 0, 2 * D1 * sizeof(float));
        k_edge<<<EDGE_GRID, 256, EDGE_SMEM>>>(ea,
                                              mlp_W1 + l * 64 * 50, mlp_b1 + l * 64,
                                              mlp_W2 + l * 64 * 64, mlp_b2 + l * 64);
        k_node<<<(N_NODES + 127) / 128, 256, NODE_SMEM>>>(cf_W2 + l * 64 * 64, cf_b2 + l * 64,
                                                          int_W + l * 64 * 64, int_b + l * 64);
        k_bn<<<(N_NODES * D1 + 255) / 256, 256>>>(bn_g + l * 64, bn_b + l * 64);
    }

    k_pool<<<(N_NODES * D1 + 255) / 256, 256>>>(batch);
    k_head<<<N_GRAPHS, 64>>>(post_W, post_b, out_W, out_b, y);
}

// round 5
// speedup vs baseline: 1.2242x; 1.0281x over previous
#include <cuda_runtime.h>
#include <math_constants.h>

#define N_NODES 50000
#define N_EDGES 1200000
#define N_GRAPHS 512
#define D1 64
#define NF 92
#define NG 50
#define BN_EPS 1e-5f
#define LOG2F_C 0.6931471805599453f

#define N_TILES (N_EDGES / 128)   // 9375
#define EDGE_GRID 444             // 3 CTAs/SM * 148

typedef unsigned long long ull;

// -------------------- device scratch --------------------
__device__ float g_out[N_NODES * D1];
__device__ float g_h[N_NODES * D1];
__device__ float g_agg[N_NODES * D1];
__device__ float g_bnstats[2 * D1];
__device__ float g_pool[N_GRAPHS * D1];
__device__ float g_cnt[N_GRAPHS];
__device__ int   g_hist[N_NODES];
__device__ int   g_eperm[N_EDGES];
__device__ float g_Cs[N_EDGES];
__device__ int   g_srcs[N_EDGES];
__device__ int   g_dsts[N_EDGES];

// -------------------- helpers --------------------
__device__ __forceinline__ ull ffma2(ull a, ull b, ull c) {
    ull d;
    asm("fma.rn.f32x2 %0, %1, %2, %3;" : "=l"(d) : "l"(a), "l"(b), "l"(c));
    return d;
}
__device__ __forceinline__ ull dup2(float v) {
    ull r;
    asm("mov.b64 %0, {%1, %1};" : "=l"(r) : "f"(v));
    return r;
}
__device__ __forceinline__ float f2lo(ull v) { return __uint_as_float((unsigned)(v & 0xffffffffull)); }
__device__ __forceinline__ float f2hi(ull v) { return __uint_as_float((unsigned)(v >> 32)); }

__device__ __forceinline__ float sspf(float v) {
    return fmaxf(v, 0.f) + __logf(1.f + __expf(-fabsf(v))) - LOG2F_C;
}

__device__ __forceinline__ void red4(float* p, float4 v) {
    asm volatile("red.global.add.v4.f32 [%0], {%1,%2,%3,%4};"
                 :: "l"(p), "f"(v.x), "f"(v.y), "f"(v.z), "f"(v.w) : "memory");
}

__device__ __forceinline__ void cp8(unsigned dst, const void* src) {
    asm volatile("cp.async.ca.shared.global [%0], [%1], 8;" :: "r"(dst), "l"(src));
}
__device__ __forceinline__ void cp_commit() {
    asm volatile("cp.async.commit_group;" ::: "memory");
}
__device__ __forceinline__ void cp_wait0() {
    asm volatile("cp.async.wait_group 0;" ::: "memory");
}
__device__ __forceinline__ void prefetchL2(const void* p) {
    asm volatile("prefetch.global.L2 [%0];" :: "l"(p));
}

// =====================================================================
// counting sort by dst
// =====================================================================
__global__ void k_hist(const int* __restrict__ ei) {
    int i = blockIdx.x * blockDim.x + threadIdx.x;
    if (i < N_EDGES) atomicAdd(&g_hist[ei[N_EDGES + i]], 1);
}

__global__ __launch_bounds__(1024) void k_scan() {
    __shared__ int ss[1024];
    int t = threadIdx.x;
    int lo = t * 49;
    int hi = min(lo + 49, N_NODES);
    int s = 0;
    for (int b = lo; b < hi; b++) s += g_hist[b];
    ss[t] = s;
    __syncthreads();
    for (int off = 1; off < 1024; off <<= 1) {
        int v = (t >= off) ? ss[t - off] : 0;
        __syncthreads();
        ss[t] += v;
        __syncthreads();
    }
    int run = ss[t] - s;
    for (int b = lo; b < hi; b++) {
        int c = g_hist[b];
        g_hist[b] = run;
        run += c;
    }
}

__global__ void k_scatter(const int* __restrict__ ei) {
    int i = blockIdx.x * blockDim.x + threadIdx.x;
    if (i < N_EDGES) {
        int pos = atomicAdd(&g_hist[ei[N_EDGES + i]], 1);
        g_eperm[pos] = i;
    }
}

__global__ void k_permute_meta(const int* __restrict__ ei, const float* __restrict__ ew) {
    int e = blockIdx.x * blockDim.x + threadIdx.x;
    if (e >= N_EDGES) return;
    int id = g_eperm[e];
    g_Cs[e] = 0.5f * (cospif(ew[id] * 0.125f) + 1.f);
    g_srcs[e] = ei[id];
    g_dsts[e] = ei[N_EDGES + id];
}

// =====================================================================
// pre FC: out = relu(x @ pre_W.T + pre_b)
// =====================================================================
__global__ __launch_bounds__(256) void k_pre(const float* __restrict__ x,
                                             const float* __restrict__ W,
                                             const float* __restrict__ b) {
    __shared__ float sW[64 * 93];
    int tid = threadIdx.x;
    for (int i = tid; i < 64 * 92; i += 256) {
        int f = i / 92, k = i % 92;
        sW[f * 93 + k] = W[i];
    }
    __syncthreads();
    int lane = tid & 31;
    int warp = (blockIdx.x * blockDim.x + tid) >> 5;
    int nwarps = (gridDim.x * blockDim.x) >> 5;
    float b0 = b[lane], b1 = b[lane + 32];
    for (int n = warp; n < N_NODES; n += nwarps) {
        const float* xr = x + (size_t)n * NF;
        float x0 = xr[lane];
        float x1 = xr[32 + lane];
        float x2 = (lane < 28) ? xr[64 + lane] : 0.f;
        float a0 = b0, a1 = b1;
#pragma unroll
        for (int k = 0; k < NF; k++) {
            float src = (k < 32) ? x0 : ((k < 64) ? x1 : x2);
            float xv = __shfl_sync(0xffffffffu, src, k & 31);
            a0 = fmaf(xv, sW[lane * 93 + k], a0);
            a1 = fmaf(xv, sW[(lane + 32) * 93 + k], a1);
        }
        g_out[(size_t)n * D1 + lane] = fmaxf(a0, 0.f);
        g_out[(size_t)n * D1 + lane + 32] = fmaxf(a1, 0.f);
    }
}

// =====================================================================
// lin1 (+ fused BN of previous layer): g_out_norm, g_h = out_norm @ W.T
// =====================================================================
#define LIN1_SMEM ((4096 + 16384 + 192) * 4)
__global__ __launch_bounds__(256, 2) void k_lin1(const float* __restrict__ W,
                                                 const float* __restrict__ bng,
                                                 const float* __restrict__ bnb,
                                                 int apply_bn) {
    extern __shared__ float sm[];
    float* sWt = sm;
    float* sA = sm + 4096;
    float* sSc = sm + 20480;   // 64
    float* sOf = sSc + 64;     // 64

    int tid = threadIdx.x;
    int tx = tid & 15, ty = tid >> 4;
    int n0 = blockIdx.x * 128;

    for (int i = tid; i < 64 * 64; i += 256) {
        int f = i >> 6, k = i & 63;
        sWt[k * 64 + f] = W[i];
    }
    if (tid < 64 && apply_bn) {
        const float invN = 1.f / (float)N_NODES;
        float mu = g_bnstats[tid] * invN;
        float var = fmaxf(g_bnstats[64 + tid] * invN - mu * mu, 0.f);
        float sc = rsqrtf(var + BN_EPS) * bng[tid];
        sSc[tid] = sc;
        sOf[tid] = bnb[tid] - mu * sc;
    }
    __syncthreads();

    for (int i = tid; i < 128 * 64; i += 256) {
        int e = i >> 6, k = i & 63;
        int n = n0 + e;
        float v = 0.f;
        if (n < N_NODES) {
            v = g_out[n * D1 + k];
            if (apply_bn) {
                v = v * sSc[k] + sOf[k];
                g_out[n * D1 + k] = v;   // write normalized back
            }
        }
        *(float2*)&sA[e * 128 + 2 * k] = make_float2(v, v);
    }
    __syncthreads();

    ull acc[8][2];
#pragma unroll
    for (int ii = 0; ii < 8; ii++) { acc[ii][0] = 0ull; acc[ii][1] = 0ull; }
#pragma unroll
    for (int p = 0; p < 32; p++) {
        ulonglong2 b0 = *reinterpret_cast<const ulonglong2*>(&sWt[(2 * p) * 64 + 4 * tx]);
        ulonglong2 b1 = *reinterpret_cast<const ulonglong2*>(&sWt[(2 * p + 1) * 64 + 4 * tx]);
#pragma unroll
        for (int ii = 0; ii < 8; ii++) {
            ulonglong2 a = *reinterpret_cast<const ulonglong2*>(&sA[(ty + 16 * ii) * 128 + 4 * p]);
            acc[ii][0] = ffma2(a.x, b0.x, acc[ii][0]);
            acc[ii][1] = ffma2(a.x, b0.y, acc[ii][1]);
            acc[ii][0] = ffma2(a.y, b1.x, acc[ii][0]);
            acc[ii][1] = ffma2(a.y, b1.y, acc[ii][1]);
        }
    }
#pragma unroll
    for (int ii = 0; ii < 8; ii++) {
        int n = n0 + ty + 16 * ii;
        if (n < N_NODES) {
            float4 o;
            o.x = f2lo(acc[ii][0]); o.y = f2hi(acc[ii][0]);
            o.z = f2lo(acc[ii][1]); o.w = f2hi(acc[ii][1]);
            *(float4*)&g_h[n * D1 + 4 * tx] = o;
        }
    }
}

// =====================================================================
// k_edge v5: persistent, union EA/hid buffer, warp-local sync only
// (every smem row is owned by one 8-thread group in all phases),
// 3 CTAs/SM, cp.async fill + L2 prefetch for next tile, run-compressed
// red.v4 scatter.  tx=tid&7: feats 8tx..8tx+7; ty=tid>>3: edges 4ty..4ty+3
// =====================================================================
#define EDGE_W1T   0
#define EDGE_W2T   3200
#define EDGE_BUF   7296           // [128][66] union: EA cols 0..49 / hid cols 0..63
#define EDGE_B1    15744
#define EDGE_B2    15808
#define EDGE_SMEM_WORDS 15872
#define EDGE_SMEM (EDGE_SMEM_WORDS * 4)

__global__ __launch_bounds__(256, 3) void k_edge(const float* __restrict__ EA,
                                                 const float* __restrict__ W1,
                                                 const float* __restrict__ bias1,
                                                 const float* __restrict__ W2,
                                                 const float* __restrict__ bias2) {
    extern __shared__ float sm[];
    float* sW1T = sm + EDGE_W1T;   // [50][64] k-major
    float* sW2T = sm + EDGE_W2T;   // [64][64] k-major
    float* sBuf = sm + EDGE_BUF;   // [128][66]
    float* sB1  = sm + EDGE_B1;
    float* sB2  = sm + EDGE_B2;

    int tid = threadIdx.x;
    int tx = tid & 7, ty = tid >> 3;

    for (int i = tid; i < 3200; i += 256) {
        int f = i / 50, k = i - f * 50;
        sW1T[k * 64 + f] = W1[i];
    }
    for (int i = tid; i < 4096; i += 256) {
        int f = i >> 6, k = i & 63;
        sW2T[k * 64 + f] = W2[i];
    }
    if (tid < 64) { sB1[tid] = bias1[tid]; sB2[tid] = bias2[tid]; }
    __syncthreads();   // weights ready (only CTA-wide sync in this kernel)

    int r = tid >> 1, half = tid & 1;
    int koff = half ? 26 : 0;
    int ncp = half ? 12 : 13;
    unsigned dst0 = (unsigned)__cvta_generic_to_shared(sBuf) + (unsigned)(r * 66 + koff) * 4u;

    int tile = blockIdx.x;
    int nid = 0;
    if (tile < N_TILES) nid = __ldg(&g_eperm[tile * 128 + r]);

    for (; tile < N_TILES; tile += EDGE_GRID) {
        int e0 = tile * 128;

        // ---- fill own rows (group-owned) via cp.async ----
        {
            const float* src = EA + (size_t)nid * NG + koff;
            for (int g = 0; g < ncp; g++)
                cp8(dst0 + (unsigned)g * 8u, src + 2 * g);
            cp_commit();
            cp_wait0();
        }
        __syncwarp();

        // ---- phase 1: hidden = EA @ W1T, K=50 ----
        ull acc[4][4];
#pragma unroll
        for (int j = 0; j < 4; j++)
#pragma unroll
            for (int p = 0; p < 4; p++) acc[j][p] = 0ull;

#pragma unroll 10
        for (int k = 0; k < 50; k++) {
            ulonglong2 bA = *(const ulonglong2*)&sW1T[k * 64 + 8 * tx];
            ulonglong2 bB = *(const ulonglong2*)&sW1T[k * 64 + 8 * tx + 4];
#pragma unroll
            for (int j = 0; j < 4; j++) {
                ull av = dup2(sBuf[(4 * ty + j) * 66 + k]);
                acc[j][0] = ffma2(av, bA.x, acc[j][0]);
                acc[j][1] = ffma2(av, bA.y, acc[j][1]);
                acc[j][2] = ffma2(av, bB.x, acc[j][2]);
                acc[j][3] = ffma2(av, bB.y, acc[j][3]);
            }
        }
        __syncwarp();   // group done reading EA rows

        // ---- ssp + bias -> hid into same rows (cols 0..63) ----
#pragma unroll
        for (int j = 0; j < 4; j++) {
            int e = 4 * ty + j;
#pragma unroll
            for (int p = 0; p < 4; p++) {
                float lo = sspf(f2lo(acc[j][p]) + sB1[8 * tx + 2 * p]);
                float hi = sspf(f2hi(acc[j][p]) + sB1[8 * tx + 2 * p + 1]);
                *(float2*)&sBuf[e * 66 + 8 * tx + 2 * p] = make_float2(lo, hi);
            }
        }
        __syncwarp();

        // load next tile's row id + L2 prefetch its EA row
        {
            int ntile = tile + EDGE_GRID;
            if (ntile < N_TILES) {
                nid = __ldg(&g_eperm[ntile * 128 + r]);
                const char* p = (const char*)(EA + (size_t)nid * NG);
                prefetchL2(p);
                prefetchL2(p + 128);
            }
        }

        // ---- phase 2: w = hid @ W2T, K=64 ----
        ull wacc[4][4];
#pragma unroll
        for (int j = 0; j < 4; j++)
#pragma unroll
            for (int p = 0; p < 4; p++) wacc[j][p] = 0ull;

#pragma unroll 8
        for (int k = 0; k < 64; k++) {
            ulonglong2 bA = *(const ulonglong2*)&sW2T[k * 64 + 8 * tx];
            ulonglong2 bB = *(const ulonglong2*)&sW2T[k * 64 + 8 * tx + 4];
#pragma unroll
            for (int j = 0; j < 4; j++) {
                ull av = dup2(sBuf[(4 * ty + j) * 66 + k]);
                wacc[j][0] = ffma2(av, bA.x, wacc[j][0]);
                wacc[j][1] = ffma2(av, bA.y, wacc[j][1]);
                wacc[j][2] = ffma2(av, bB.x, wacc[j][2]);
                wacc[j][3] = ffma2(av, bB.y, wacc[j][3]);
            }
        }
        __syncwarp();   // group done reading hid rows (buffer free next iter)

        // ---- phase 3: bias + cutoff + gather h[src] + run-compressed scatter ----
        float b20 = sB2[8 * tx + 0], b21 = sB2[8 * tx + 1];
        float b22 = sB2[8 * tx + 2], b23 = sB2[8 * tx + 3];
        float b24 = sB2[8 * tx + 4], b25 = sB2[8 * tx + 5];
        float b26 = sB2[8 * tx + 6], b27 = sB2[8 * tx + 7];
        int cur = -1;
        float4 r0 = make_float4(0.f, 0.f, 0.f, 0.f);
        float4 r1 = make_float4(0.f, 0.f, 0.f, 0.f);
#pragma unroll
        for (int j = 0; j < 4; j++) {
            int ge = e0 + 4 * ty + j;
            float cc = __ldg(&g_Cs[ge]);
            int sn = __ldg(&g_srcs[ge]);
            int dn = __ldg(&g_dsts[ge]);
            float4 h0 = *(const float4*)&g_h[(size_t)sn * D1 + 8 * tx];
            float4 h1 = *(const float4*)&g_h[(size_t)sn * D1 + 8 * tx + 4];
            float4 m0, m1;
            m0.x = (f2lo(wacc[j][0]) + b20) * cc * h0.x;
            m0.y = (f2hi(wacc[j][0]) + b21) * cc * h0.y;
            m0.z = (f2lo(wacc[j][1]) + b22) * cc * h0.z;
            m0.w = (f2hi(wacc[j][1]) + b23) * cc * h0.w;
            m1.x = (f2lo(wacc[j][2]) + b24) * cc * h1.x;
            m1.y = (f2hi(wacc[j][2]) + b25) * cc * h1.y;
            m1.z = (f2lo(wacc[j][3]) + b26) * cc * h1.z;
            m1.w = (f2hi(wacc[j][3]) + b27) * cc * h1.w;
            if (j == 0) {
                cur = dn; r0 = m0; r1 = m1;
            } else if (dn == cur) {
                r0.x += m0.x; r0.y += m0.y; r0.z += m0.z; r0.w += m0.w;
                r1.x += m1.x; r1.y += m1.y; r1.z += m1.z; r1.w += m1.w;
            } else {
                red4(&g_agg[(size_t)cur * D1 + 8 * tx], r0);
                red4(&g_agg[(size_t)cur * D1 + 8 * tx + 4], r1);
                cur = dn; r0 = m0; r1 = m1;
            }
        }
        red4(&g_agg[(size_t)cur * D1 + 8 * tx], r0);
        red4(&g_agg[(size_t)cur * D1 + 8 * tx + 4], r1);
    }
}

// =====================================================================
// node kernel: t = ssp(agg @ cf_W2.T + cf_b2) @ int_W.T + int_b
//              out += t; accumulate BN stats
// =====================================================================
#define NODE_SMEM ((4096 + 4096 + 16384 + 64 + 64 + 64 + 64) * 4)
__global__ __launch_bounds__(256, 2) void k_node(const float* __restrict__ Wa,
                                                 const float* __restrict__ ba,
                                                 const float* __restrict__ Wb,
                                                 const float* __restrict__ bb) {
    extern __shared__ float sm[];
    float* sWat = sm;
    float* sWbt = sm + 4096;
    float* sA = sm + 8192;
    float* sBa = sm + 24576;
    float* sBb = sBa + 64;
    float* sSum = sBb + 64;
    float* sSq = sSum + 64;

    int tid = threadIdx.x;
    int tx = tid & 15, ty = tid >> 4;
    int n0 = blockIdx.x * 128;

    for (int i = tid; i < 64 * 64; i += 256) {
        int f = i >> 6, k = i & 63;
        sWat[k * 64 + f] = Wa[i];
        sWbt[k * 64 + f] = Wb[i];
    }
    if (tid < 64) { sBa[tid] = ba[tid]; sBb[tid] = bb[tid]; sSum[tid] = 0.f; sSq[tid] = 0.f; }
    for (int i = tid; i < 128 * 64; i += 256) {
        int e = i >> 6, k = i & 63;
        int n = n0 + e;
        float v = (n < N_NODES) ? g_agg[n * D1 + k] : 0.f;
        *(float2*)&sA[e * 128 + 2 * k] = make_float2(v, v);
    }
    __syncthreads();

    ull acc[8][2];
#pragma unroll
    for (int ii = 0; ii < 8; ii++) { acc[ii][0] = 0ull; acc[ii][1] = 0ull; }
#pragma unroll
    for (int p = 0; p < 32; p++) {
        ulonglong2 b0 = *reinterpret_cast<const ulonglong2*>(&sWat[(2 * p) * 64 + 4 * tx]);
        ulonglong2 b1 = *reinterpret_cast<const ulonglong2*>(&sWat[(2 * p + 1) * 64 + 4 * tx]);
#pragma unroll
        for (int ii = 0; ii < 8; ii++) {
            ulonglong2 a = *reinterpret_cast<const ulonglong2*>(&sA[(ty + 16 * ii) * 128 + 4 * p]);
            acc[ii][0] = ffma2(a.x, b0.x, acc[ii][0]);
            acc[ii][1] = ffma2(a.x, b0.y, acc[ii][1]);
            acc[ii][0] = ffma2(a.y, b1.x, acc[ii][0]);
            acc[ii][1] = ffma2(a.y, b1.y, acc[ii][1]);
        }
    }
    __syncthreads();

    float bb0 = sBa[4 * tx + 0], bb1 = sBa[4 * tx + 1];
    float bb2 = sBa[4 * tx + 2], bb3 = sBa[4 * tx + 3];
#pragma unroll
    for (int ii = 0; ii < 8; ii++) {
        int e = ty + 16 * ii;
        float h0 = sspf(f2lo(acc[ii][0]) + bb0);
        float h1 = sspf(f2hi(acc[ii][0]) + bb1);
        float h2 = sspf(f2lo(acc[ii][1]) + bb2);
        float h3 = sspf(f2hi(acc[ii][1]) + bb3);
        float2* p = (float2*)&sA[e * 128 + 8 * tx];
        p[0] = make_float2(h0, h0);
        p[1] = make_float2(h1, h1);
        p[2] = make_float2(h2, h2);
        p[3] = make_float2(h3, h3);
    }
    __syncthreads();

    ull wacc[8][2];
#pragma unroll
    for (int ii = 0; ii < 8; ii++) { wacc[ii][0] = 0ull; wacc[ii][1] = 0ull; }
#pragma unroll
    for (int p = 0; p < 32; p++) {
        ulonglong2 b0 = *reinterpret_cast<const ulonglong2*>(&sWbt[(2 * p) * 64 + 4 * tx]);
        ulonglong2 b1 = *reinterpret_cast<const ulonglong2*>(&sWbt[(2 * p + 1) * 64 + 4 * tx]);
#pragma unroll
        for (int ii = 0; ii < 8; ii++) {
            ulonglong2 a = *reinterpret_cast<const ulonglong2*>(&sA[(ty + 16 * ii) * 128 + 4 * p]);
            wacc[ii][0] = ffma2(a.x, b0.x, wacc[ii][0]);
            wacc[ii][1] = ffma2(a.x, b0.y, wacc[ii][1]);
            wacc[ii][0] = ffma2(a.y, b1.x, wacc[ii][0]);
            wacc[ii][1] = ffma2(a.y, b1.y, wacc[ii][1]);
        }
    }

    float c0 = sBb[4 * tx + 0], c1 = sBb[4 * tx + 1];
    float c2 = sBb[4 * tx + 2], c3 = sBb[4 * tx + 3];
    float ps0 = 0.f, ps1 = 0.f, ps2 = 0.f, ps3 = 0.f;
    float pq0 = 0.f, pq1 = 0.f, pq2 = 0.f, pq3 = 0.f;
#pragma unroll
    for (int ii = 0; ii < 8; ii++) {
        int n = n0 + ty + 16 * ii;
        if (n < N_NODES) {
            float4 prev = *(const float4*)&g_out[n * D1 + 4 * tx];
            float r0 = f2lo(wacc[ii][0]) + c0 + prev.x;
            float r1 = f2hi(wacc[ii][0]) + c1 + prev.y;
            float r2 = f2lo(wacc[ii][1]) + c2 + prev.z;
            float r3 = f2hi(wacc[ii][1]) + c3 + prev.w;
            float4 o; o.x = r0; o.y = r1; o.z = r2; o.w = r3;
            *(float4*)&g_out[n * D1 + 4 * tx] = o;
            ps0 += r0; ps1 += r1; ps2 += r2; ps3 += r3;
            pq0 += r0 * r0; pq1 += r1 * r1; pq2 += r2 * r2; pq3 += r3 * r3;
        }
    }
    atomicAdd(&sSum[4 * tx + 0], ps0); atomicAdd(&sSum[4 * tx + 1], ps1);
    atomicAdd(&sSum[4 * tx + 2], ps2); atomicAdd(&sSum[4 * tx + 3], ps3);
    atomicAdd(&sSq[4 * tx + 0], pq0);  atomicAdd(&sSq[4 * tx + 1], pq1);
    atomicAdd(&sSq[4 * tx + 2], pq2);  atomicAdd(&sSq[4 * tx + 3], pq3);
    __syncthreads();
    if (tid < 64) {
        atomicAdd(&g_bnstats[tid], sSum[tid]);
        atomicAdd(&g_bnstats[64 + tid], sSq[tid]);
    }
}

// =====================================================================
// pool with fused layer-2 BN
// =====================================================================
__global__ __launch_bounds__(256) void k_pool(const int* __restrict__ batch,
                                              const float* __restrict__ bng,
                                              const float* __restrict__ bnb) {
    __shared__ float sSc[64], sOf[64];
    int tid = threadIdx.x;
    if (tid < 64) {
        const float invN = 1.f / (float)N_NODES;
        float mu = g_bnstats[tid] * invN;
        float var = fmaxf(g_bnstats[64 + tid] * invN - mu * mu, 0.f);
        float sc = rsqrtf(var + BN_EPS) * bng[tid];
        sSc[tid] = sc;
        sOf[tid] = bnb[tid] - mu * sc;
    }
    __syncthreads();
    int idx = blockIdx.x * blockDim.x + tid;
    if (idx >= N_NODES * D1) return;
    int n = idx >> 6, f = idx & 63;
    int bg = batch[n];
    float v = g_out[idx] * sSc[f] + sOf[f];
    atomicAdd(&g_pool[bg * D1 + f], v);
    if (f == 0) atomicAdd(&g_cnt[bg], 1.f);
}

__global__ void k_head(const float* __restrict__ postW, const float* __restrict__ postb,
                       const float* __restrict__ outW, const float* __restrict__ outb,
                       float* __restrict__ y) {
    int g = blockIdx.x;
    int f = threadIdx.x;
    __shared__ float sp[64];
    __shared__ float sr[2];
    float cnt = fmaxf(g_cnt[g], 1.f);
    sp[f] = g_pool[g * D1 + f] / cnt;
    __syncthreads();
    float a = postb[f];
#pragma unroll
    for (int k = 0; k < 64; k++) a = fmaf(sp[k], postW[f * 64 + k], a);
    float hp = fmaxf(a, 0.f) * outW[f];
#pragma unroll
    for (int o = 16; o > 0; o >>= 1) hp += __shfl_down_sync(0xffffffffu, hp, o);
    if ((f & 31) == 0) sr[f >> 5] = hp;
    __syncthreads();
    if (f == 0) y[g] = sr[0] + sr[1] + outb[0];
}

// =====================================================================
extern "C" void kernel_launch(void* const* d_in, const int* in_sizes, int n_in,
                              void* d_out, int out_size) {
    const float* x      = (const float*)d_in[0];
    const float* ew     = (const float*)d_in[1];
    const float* ea     = (const float*)d_in[2];
    const int*   ei     = (const int*)d_in[3];
    const int*   batch  = (const int*)d_in[4];
    const float* pre_W  = (const float*)d_in[5];
    const float* pre_b  = (const float*)d_in[6];
    const float* mlp_W1 = (const float*)d_in[7];
    const float* mlp_b1 = (const float*)d_in[8];
    const float* mlp_W2 = (const float*)d_in[9];
    const float* mlp_b2 = (const float*)d_in[10];
    const float* cf_W1  = (const float*)d_in[11];
    const float* cf_W2  = (const float*)d_in[12];
    const float* cf_b2  = (const float*)d_in[13];
    const float* int_W  = (const float*)d_in[14];
    const float* int_b  = (const float*)d_in[15];
    const float* bn_g   = (const float*)d_in[16];
    const float* bn_b   = (const float*)d_in[17];
    const float* post_W = (const float*)d_in[18];
    const float* post_b = (const float*)d_in[19];
    const float* out_W  = (const float*)d_in[20];
    const float* out_b  = (const float*)d_in[21];
    float* y = (float*)d_out;

    void *agg_p, *bn_p, *pool_p, *cnt_p, *hist_p;
    cudaGetSymbolAddress(&agg_p, g_agg);
    cudaGetSymbolAddress(&bn_p, g_bnstats);
    cudaGetSymbolAddress(&pool_p, g_pool);
    cudaGetSymbolAddress(&cnt_p, g_cnt);
    cudaGetSymbolAddress(&hist_p, g_hist);

    cudaFuncSetAttribute(k_edge, cudaFuncAttributeMaxDynamicSharedMemorySize, EDGE_SMEM);
    cudaFuncSetAttribute(k_node, cudaFuncAttributeMaxDynamicSharedMemorySize, NODE_SMEM);
    cudaFuncSetAttribute(k_lin1, cudaFuncAttributeMaxDynamicSharedMemorySize, LIN1_SMEM);

    // counting sort of edges by dst + sorted meta
    cudaMemsetAsync(hist_p, 0, N_NODES * sizeof(int));
    k_hist<<<(N_EDGES + 255) / 256, 256>>>(ei);
    k_scan<<<1, 1024>>>();
    k_scatter<<<(N_EDGES + 255) / 256, 256>>>(ei);
    k_permute_meta<<<(N_EDGES + 255) / 256, 256>>>(ei, ew);

    k_pre<<<512, 256>>>(x, pre_W, pre_b);
    cudaMemsetAsync(pool_p, 0, N_GRAPHS * D1 * sizeof(float));
    cudaMemsetAsync(cnt_p, 0, N_GRAPHS * sizeof(float));

    for (int l = 0; l < 3; l++) {
        // lin1 applies BN of previous layer (none for l=0)
        k_lin1<<<(N_NODES + 127) / 128, 256, LIN1_SMEM>>>(
            cf_W1 + l * 64 * 64,
            bn_g + (l > 0 ? (l - 1) * 64 : 0),
            bn_b + (l > 0 ? (l - 1) * 64 : 0),
            l > 0 ? 1 : 0);
        cudaMemsetAsync(agg_p, 0, (size_t)N_NODES * D1 * sizeof(float));
        cudaMemsetAsync(bn_p, 0, 2 * D1 * sizeof(float));
        k_edge<<<EDGE_GRID, 256, EDGE_SMEM>>>(ea,
                                              mlp_W1 + l * 64 * 50, mlp_b1 + l * 64,
                                              mlp_W2 + l * 64 * 64, mlp_b2 + l * 64);
        k_node<<<(N_NODES + 127) / 128, 256, NODE_SMEM>>>(cf_W2 + l * 64 * 64, cf_b2 + l * 64,
                                                          int_W + l * 64 * 64, int_b + l * 64);
    }

    // pool applies layer-2 BN inline
    k_pool<<<(N_NODES * D1 + 255) / 256, 256>>>(batch, bn_g + 2 * 64, bn_b + 2 * 64);
    k_head<<<N_GRAPHS, 64>>>(post_W, post_b, out_W, out_b, y);
}

// round 6
// speedup vs baseline: 2.1036x; 1.7183x over previous
#include <cuda_runtime.h>
#include <math_constants.h>

#define N_NODES 50000
#define N_EDGES 1200000
#define N_GRAPHS 512
#define D1 64
#define NF 92
#define NG 50
#define BN_EPS 1e-5f
#define LOG2F_C 0.6931471805599453f

#define N_TILES (N_EDGES / 128)   // 9375
#define EDGE_GRID 444             // 3 CTAs/SM * 148

typedef unsigned long long ull;

// -------------------- device scratch --------------------
__device__ float g_out[N_NODES * D1];
__device__ float g_h[N_NODES * D1];
__device__ float g_agg[N_NODES * D1];
__device__ float g_bnstats[2 * D1];
__device__ float g_pool[N_GRAPHS * D1];
__device__ float g_cnt[N_GRAPHS];
__device__ int   g_hist[N_NODES];
__device__ int   g_eperm[N_EDGES];
__device__ float g_Cs[N_EDGES];
__device__ int   g_srcs[N_EDGES];
__device__ int   g_dsts[N_EDGES];

// -------------------- helpers --------------------
__device__ __forceinline__ ull ffma2(ull a, ull b, ull c) {
    ull d;
    asm("fma.rn.f32x2 %0, %1, %2, %3;" : "=l"(d) : "l"(a), "l"(b), "l"(c));
    return d;
}
__device__ __forceinline__ float f2lo(ull v) { return __uint_as_float((unsigned)(v & 0xffffffffull)); }
__device__ __forceinline__ float f2hi(ull v) { return __uint_as_float((unsigned)(v >> 32)); }

__device__ __forceinline__ float sspf(float v) {
    return fmaxf(v, 0.f) + __logf(1.f + __expf(-fabsf(v))) - LOG2F_C;
}

__device__ __forceinline__ void red4(float* p, float4 v) {
    asm volatile("red.global.add.v4.f32 [%0], {%1,%2,%3,%4};"
                 :: "l"(p), "f"(v.x), "f"(v.y), "f"(v.z), "f"(v.w) : "memory");
}

__device__ __forceinline__ void cp8(unsigned dst, const void* src) {
    asm volatile("cp.async.ca.shared.global [%0], [%1], 8;" :: "r"(dst), "l"(src));
}
__device__ __forceinline__ void cp_commit() {
    asm volatile("cp.async.commit_group;" ::: "memory");
}
__device__ __forceinline__ void cp_wait0() {
    asm volatile("cp.async.wait_group 0;" ::: "memory");
}
__device__ __forceinline__ void prefetchL2(const void* p) {
    asm volatile("prefetch.global.L2 [%0];" :: "l"(p));
}
__device__ __forceinline__ unsigned tf32bits(float v) {
    unsigned r;
    asm("cvt.rna.tf32.f32 %0, %1;" : "=r"(r) : "f"(v));
    return r;
}
__device__ __forceinline__ void mma_tf32(float& c0, float& c1, float& c2, float& c3,
                                         unsigned a0, unsigned a1, unsigned a2, unsigned a3,
                                         unsigned b0, unsigned b1) {
    asm volatile("mma.sync.aligned.m16n8k8.row.col.f32.tf32.tf32.f32 "
                 "{%0,%1,%2,%3}, {%4,%5,%6,%7}, {%8,%9}, {%0,%1,%2,%3};"
                 : "+f"(c0), "+f"(c1), "+f"(c2), "+f"(c3)
                 : "r"(a0), "r"(a1), "r"(a2), "r"(a3), "r"(b0), "r"(b1));
}

// =====================================================================
// counting sort by dst
// =====================================================================
__global__ void k_hist(const int* __restrict__ ei) {
    int i = blockIdx.x * blockDim.x + threadIdx.x;
    if (i < N_EDGES) atomicAdd(&g_hist[ei[N_EDGES + i]], 1);
}

__global__ __launch_bounds__(1024) void k_scan() {
    __shared__ int ss[1024];
    int t = threadIdx.x;
    int lo = t * 49;
    int hi = min(lo + 49, N_NODES);
    int s = 0;
    for (int b = lo; b < hi; b++) s += g_hist[b];
    ss[t] = s;
    __syncthreads();
    for (int off = 1; off < 1024; off <<= 1) {
        int v = (t >= off) ? ss[t - off] : 0;
        __syncthreads();
        ss[t] += v;
        __syncthreads();
    }
    int run = ss[t] - s;
    for (int b = lo; b < hi; b++) {
        int c = g_hist[b];
        g_hist[b] = run;
        run += c;
    }
}

__global__ void k_scatter(const int* __restrict__ ei) {
    int i = blockIdx.x * blockDim.x + threadIdx.x;
    if (i < N_EDGES) {
        int pos = atomicAdd(&g_hist[ei[N_EDGES + i]], 1);
        g_eperm[pos] = i;
    }
}

__global__ void k_permute_meta(const int* __restrict__ ei, const float* __restrict__ ew) {
    int e = blockIdx.x * blockDim.x + threadIdx.x;
    if (e >= N_EDGES) return;
    int id = g_eperm[e];
    g_Cs[e] = 0.5f * (cospif(ew[id] * 0.125f) + 1.f);
    g_srcs[e] = ei[id];
    g_dsts[e] = ei[N_EDGES + id];
}

// =====================================================================
// pre FC: out = relu(x @ pre_W.T + pre_b)
// =====================================================================
__global__ __launch_bounds__(256) void k_pre(const float* __restrict__ x,
                                             const float* __restrict__ W,
                                             const float* __restrict__ b) {
    __shared__ float sW[64 * 93];
    int tid = threadIdx.x;
    for (int i = tid; i < 64 * 92; i += 256) {
        int f = i / 92, k = i % 92;
        sW[f * 93 + k] = W[i];
    }
    __syncthreads();
    int lane = tid & 31;
    int warp = (blockIdx.x * blockDim.x + tid) >> 5;
    int nwarps = (gridDim.x * blockDim.x) >> 5;
    float b0 = b[lane], b1 = b[lane + 32];
    for (int n = warp; n < N_NODES; n += nwarps) {
        const float* xr = x + (size_t)n * NF;
        float x0 = xr[lane];
        float x1 = xr[32 + lane];
        float x2 = (lane < 28) ? xr[64 + lane] : 0.f;
        float a0 = b0, a1 = b1;
#pragma unroll
        for (int k = 0; k < NF; k++) {
            float src = (k < 32) ? x0 : ((k < 64) ? x1 : x2);
            float xv = __shfl_sync(0xffffffffu, src, k & 31);
            a0 = fmaf(xv, sW[lane * 93 + k], a0);
            a1 = fmaf(xv, sW[(lane + 32) * 93 + k], a1);
        }
        g_out[(size_t)n * D1 + lane] = fmaxf(a0, 0.f);
        g_out[(size_t)n * D1 + lane + 32] = fmaxf(a1, 0.f);
    }
}

// =====================================================================
// lin1 (+ fused BN of previous layer)
// =====================================================================
#define LIN1_SMEM ((4096 + 16384 + 192) * 4)
__global__ __launch_bounds__(256, 2) void k_lin1(const float* __restrict__ W,
                                                 const float* __restrict__ bng,
                                                 const float* __restrict__ bnb,
                                                 int apply_bn) {
    extern __shared__ float sm[];
    float* sWt = sm;
    float* sA = sm + 4096;
    float* sSc = sm + 20480;
    float* sOf = sSc + 64;

    int tid = threadIdx.x;
    int tx = tid & 15, ty = tid >> 4;
    int n0 = blockIdx.x * 128;

    for (int i = tid; i < 64 * 64; i += 256) {
        int f = i >> 6, k = i & 63;
        sWt[k * 64 + f] = W[i];
    }
    if (tid < 64 && apply_bn) {
        const float invN = 1.f / (float)N_NODES;
        float mu = g_bnstats[tid] * invN;
        float var = fmaxf(g_bnstats[64 + tid] * invN - mu * mu, 0.f);
        float sc = rsqrtf(var + BN_EPS) * bng[tid];
        sSc[tid] = sc;
        sOf[tid] = bnb[tid] - mu * sc;
    }
    __syncthreads();

    for (int i = tid; i < 128 * 64; i += 256) {
        int e = i >> 6, k = i & 63;
        int n = n0 + e;
        float v = 0.f;
        if (n < N_NODES) {
            v = g_out[n * D1 + k];
            if (apply_bn) {
                v = v * sSc[k] + sOf[k];
                g_out[n * D1 + k] = v;
            }
        }
        *(float2*)&sA[e * 128 + 2 * k] = make_float2(v, v);
    }
    __syncthreads();

    ull acc[8][2];
#pragma unroll
    for (int ii = 0; ii < 8; ii++) { acc[ii][0] = 0ull; acc[ii][1] = 0ull; }
#pragma unroll
    for (int p = 0; p < 32; p++) {
        ulonglong2 b0 = *reinterpret_cast<const ulonglong2*>(&sWt[(2 * p) * 64 + 4 * tx]);
        ulonglong2 b1 = *reinterpret_cast<const ulonglong2*>(&sWt[(2 * p + 1) * 64 + 4 * tx]);
#pragma unroll
        for (int ii = 0; ii < 8; ii++) {
            ulonglong2 a = *reinterpret_cast<const ulonglong2*>(&sA[(ty + 16 * ii) * 128 + 4 * p]);
            acc[ii][0] = ffma2(a.x, b0.x, acc[ii][0]);
            acc[ii][1] = ffma2(a.x, b0.y, acc[ii][1]);
            acc[ii][0] = ffma2(a.y, b1.x, acc[ii][0]);
            acc[ii][1] = ffma2(a.y, b1.y, acc[ii][1]);
        }
    }
#pragma unroll
    for (int ii = 0; ii < 8; ii++) {
        int n = n0 + ty + 16 * ii;
        if (n < N_NODES) {
            float4 o;
            o.x = f2lo(acc[ii][0]); o.y = f2hi(acc[ii][0]);
            o.z = f2lo(acc[ii][1]); o.w = f2hi(acc[ii][1]);
            *(float4*)&g_h[n * D1 + 4 * tx] = o;
        }
    }
}

// =====================================================================
// k_edge v6: tf32 tensor-core edge pipeline.
// Warp owns 16-edge stripe: cp.async EA fill -> mma GEMM1 (K=56, padded)
// -> ssp -> smem -> mma GEMM2 (K=64) -> smem -> run-compressed red.v4.
// smem stride 68 => conflict-free A/B fragment LDS.
// =====================================================================
#define EDGE_SW1   0
#define EDGE_SW2   3808              // 56*68
#define EDGE_BUF   8160              // +64*68
#define EDGE_B1    16864             // +128*68
#define EDGE_B2    16928
#define EDGE_SMEM_WORDS 16992
#define EDGE_SMEM (EDGE_SMEM_WORDS * 4)

__global__ __launch_bounds__(256, 3) void k_edge(const float* __restrict__ EA,
                                                 const float* __restrict__ W1,
                                                 const float* __restrict__ bias1,
                                                 const float* __restrict__ W2,
                                                 const float* __restrict__ bias2) {
    extern __shared__ float sm[];
    float* sW1T = sm + EDGE_SW1;   // [56][68]  B for GEMM1 (k-major), tf32
    float* sW2T = sm + EDGE_SW2;   // [64][68]  B for GEMM2 (k-major), tf32
    float* sBuf = sm + EDGE_BUF;   // [128][68] EA / hid / W union
    float* sB1  = sm + EDGE_B1;
    float* sB2  = sm + EDGE_B2;

    int tid = threadIdx.x;
    int lane = tid & 31;
    int w = tid >> 5;              // 8 warps, warp w owns rows 16w..16w+15
    int g = lane >> 2, t = lane & 3;
    int R0 = 16 * w;

    // ---- stage weights (tf32-rounded), biases; zero sBuf ----
    for (int i = tid; i < 56 * 64; i += 256) {
        int k = i >> 6, f = i & 63;
        float v = (k < 50) ? W1[f * 50 + k] : 0.f;
        sW1T[k * 68 + f] = __uint_as_float(tf32bits(v));
    }
    for (int i = tid; i < 64 * 64; i += 256) {
        int k = i >> 6, f = i & 63;
        sW2T[k * 68 + f] = __uint_as_float(tf32bits(W2[f * 64 + k]));
    }
    if (tid < 64) { sB1[tid] = bias1[tid]; sB2[tid] = bias2[tid]; }
    for (int i = tid; i < 128 * 68; i += 256) sBuf[i] = 0.f;
    __syncthreads();

    // fill assignment: 2 lanes per row
    int frow = lane >> 1, fhalf = lane & 1;
    int koff = fhalf ? 26 : 0;
    int ncp = fhalf ? 12 : 13;
    unsigned fdst = (unsigned)__cvta_generic_to_shared(sBuf)
                  + (unsigned)((R0 + frow) * 68 + koff) * 4u;

    const float* aRow0 = sBuf + (R0 + g) * 68;
    const float* aRow8 = sBuf + (R0 + g + 8) * 68;

    for (int tile = blockIdx.x; tile < N_TILES; tile += EDGE_GRID) {
        int e0 = tile * 128;

        // ---- fill own EA rows ----
        {
            int nid = __ldg(&g_eperm[e0 + R0 + frow]);
            const float* src = EA + (size_t)nid * NG + koff;
            for (int q = 0; q < ncp; q++)
                cp8(fdst + (unsigned)q * 8u, src + 2 * q);
            cp_commit();
            cp_wait0();
        }
        __syncwarp();

        // ---- GEMM1: hid = EA @ W1T, K=56 (cols 50..55 zero-weighted) ----
        float c[8][4];
#pragma unroll
        for (int nb = 0; nb < 8; nb++)
#pragma unroll
            for (int q = 0; q < 4; q++) c[nb][q] = 0.f;

#pragma unroll
        for (int kk = 0; kk < 7; kk++) {
            int kb = kk * 8;
            unsigned a0 = tf32bits(aRow0[kb + t]);
            unsigned a1 = tf32bits(aRow8[kb + t]);
            unsigned a2 = tf32bits(aRow0[kb + t + 4]);
            unsigned a3 = tf32bits(aRow8[kb + t + 4]);
#pragma unroll
            for (int nb = 0; nb < 8; nb++) {
                unsigned b0 = __float_as_uint(sW1T[(kb + t) * 68 + nb * 8 + g]);
                unsigned b1 = __float_as_uint(sW1T[(kb + t + 4) * 68 + nb * 8 + g]);
                mma_tf32(c[nb][0], c[nb][1], c[nb][2], c[nb][3], a0, a1, a2, a3, b0, b1);
            }
        }
        __syncwarp();

        // ---- ssp + bias -> sBuf (fp32) ----
#pragma unroll
        for (int nb = 0; nb < 8; nb++) {
            int col = nb * 8 + 2 * t;
            float bl = sB1[col], bh = sB1[col + 1];
            *(float2*)&sBuf[(R0 + g) * 68 + col] =
                make_float2(sspf(c[nb][0] + bl), sspf(c[nb][1] + bh));
            *(float2*)&sBuf[(R0 + g + 8) * 68 + col] =
                make_float2(sspf(c[nb][2] + bl), sspf(c[nb][3] + bh));
        }
        __syncwarp();

        // L2 prefetch next tile's EA rows
        {
            int ntile = tile + EDGE_GRID;
            if (ntile < N_TILES) {
                int nn = __ldg(&g_eperm[ntile * 128 + R0 + frow]);
                const char* p = (const char*)(EA + (size_t)nn * NG);
                prefetchL2(p);
                prefetchL2(p + 128);
            }
        }

        // ---- GEMM2: Wf = hid @ W2T, K=64 ----
        float d[8][4];
#pragma unroll
        for (int nb = 0; nb < 8; nb++)
#pragma unroll
            for (int q = 0; q < 4; q++) d[nb][q] = 0.f;

#pragma unroll
        for (int kk = 0; kk < 8; kk++) {
            int kb = kk * 8;
            unsigned a0 = tf32bits(aRow0[kb + t]);
            unsigned a1 = tf32bits(aRow8[kb + t]);
            unsigned a2 = tf32bits(aRow0[kb + t + 4]);
            unsigned a3 = tf32bits(aRow8[kb + t + 4]);
#pragma unroll
            for (int nb = 0; nb < 8; nb++) {
                unsigned b0 = __float_as_uint(sW2T[(kb + t) * 68 + nb * 8 + g]);
                unsigned b1 = __float_as_uint(sW2T[(kb + t + 4) * 68 + nb * 8 + g]);
                mma_tf32(d[nb][0], d[nb][1], d[nb][2], d[nb][3], a0, a1, a2, a3, b0, b1);
            }
        }
        __syncwarp();

        // ---- store raw filter W to sBuf ----
#pragma unroll
        for (int nb = 0; nb < 8; nb++) {
            int col = nb * 8 + 2 * t;
            *(float2*)&sBuf[(R0 + g) * 68 + col] = make_float2(d[nb][0], d[nb][1]);
            *(float2*)&sBuf[(R0 + g + 8) * 68 + col] = make_float2(d[nb][2], d[nb][3]);
        }
        __syncwarp();

        // ---- scatter: bias + cutoff + gather h[src] + run-compressed red.v4 ----
        {
            int g2 = lane >> 3, tx = lane & 7;
            float4 bb0 = *(const float4*)&sB2[8 * tx];
            float4 bb1 = *(const float4*)&sB2[8 * tx + 4];
            int cur = -1;
            float4 r0 = make_float4(0.f, 0.f, 0.f, 0.f);
            float4 r1 = make_float4(0.f, 0.f, 0.f, 0.f);
#pragma unroll
            for (int j = 0; j < 4; j++) {
                int le = R0 + 4 * g2 + j;
                int ge = e0 + le;
                float cc = __ldg(&g_Cs[ge]);
                int sn = __ldg(&g_srcs[ge]);
                int dn = __ldg(&g_dsts[ge]);
                float4 w0 = *(const float4*)&sBuf[le * 68 + 8 * tx];
                float4 w1 = *(const float4*)&sBuf[le * 68 + 8 * tx + 4];
                float4 h0 = *(const float4*)&g_h[(size_t)sn * D1 + 8 * tx];
                float4 h1 = *(const float4*)&g_h[(size_t)sn * D1 + 8 * tx + 4];
                float4 m0, m1;
                m0.x = (w0.x + bb0.x) * cc * h0.x;
                m0.y = (w0.y + bb0.y) * cc * h0.y;
                m0.z = (w0.z + bb0.z) * cc * h0.z;
                m0.w = (w0.w + bb0.w) * cc * h0.w;
                m1.x = (w1.x + bb1.x) * cc * h1.x;
                m1.y = (w1.y + bb1.y) * cc * h1.y;
                m1.z = (w1.z + bb1.z) * cc * h1.z;
                m1.w = (w1.w + bb1.w) * cc * h1.w;
                if (j == 0) {
                    cur = dn; r0 = m0; r1 = m1;
                } else if (dn == cur) {
                    r0.x += m0.x; r0.y += m0.y; r0.z += m0.z; r0.w += m0.w;
                    r1.x += m1.x; r1.y += m1.y; r1.z += m1.z; r1.w += m1.w;
                } else {
                    red4(&g_agg[(size_t)cur * D1 + 8 * tx], r0);
                    red4(&g_agg[(size_t)cur * D1 + 8 * tx + 4], r1);
                    cur = dn; r0 = m0; r1 = m1;
                }
            }
            red4(&g_agg[(size_t)cur * D1 + 8 * tx], r0);
            red4(&g_agg[(size_t)cur * D1 + 8 * tx + 4], r1);
        }
        __syncwarp();   // sBuf reads done before next tile's fill
    }
}

// =====================================================================
// node kernel: t = ssp(agg @ cf_W2.T + cf_b2) @ int_W.T + int_b
//              out += t; accumulate BN stats
// =====================================================================
#define NODE_SMEM ((4096 + 4096 + 16384 + 64 + 64 + 64 + 64) * 4)
__global__ __launch_bounds__(256, 2) void k_node(const float* __restrict__ Wa,
                                                 const float* __restrict__ ba,
                                                 const float* __restrict__ Wb,
                                                 const float* __restrict__ bb) {
    extern __shared__ float sm[];
    float* sWat = sm;
    float* sWbt = sm + 4096;
    float* sA = sm + 8192;
    float* sBa = sm + 24576;
    float* sBb = sBa + 64;
    float* sSum = sBb + 64;
    float* sSq = sSum + 64;

    int tid = threadIdx.x;
    int tx = tid & 15, ty = tid >> 4;
    int n0 = blockIdx.x * 128;

    for (int i = tid; i < 64 * 64; i += 256) {
        int f = i >> 6, k = i & 63;
        sWat[k * 64 + f] = Wa[i];
        sWbt[k * 64 + f] = Wb[i];
    }
    if (tid < 64) { sBa[tid] = ba[tid]; sBb[tid] = bb[tid]; sSum[tid] = 0.f; sSq[tid] = 0.f; }
    for (int i = tid; i < 128 * 64; i += 256) {
        int e = i >> 6, k = i & 63;
        int n = n0 + e;
        float v = (n < N_NODES) ? g_agg[n * D1 + k] : 0.f;
        *(float2*)&sA[e * 128 + 2 * k] = make_float2(v, v);
    }
    __syncthreads();

    ull acc[8][2];
#pragma unroll
    for (int ii = 0; ii < 8; ii++) { acc[ii][0] = 0ull; acc[ii][1] = 0ull; }
#pragma unroll
    for (int p = 0; p < 32; p++) {
        ulonglong2 b0 = *reinterpret_cast<const ulonglong2*>(&sWat[(2 * p) * 64 + 4 * tx]);
        ulonglong2 b1 = *reinterpret_cast<const ulonglong2*>(&sWat[(2 * p + 1) * 64 + 4 * tx]);
#pragma unroll
        for (int ii = 0; ii < 8; ii++) {
            ulonglong2 a = *reinterpret_cast<const ulonglong2*>(&sA[(ty + 16 * ii) * 128 + 4 * p]);
            acc[ii][0] = ffma2(a.x, b0.x, acc[ii][0]);
            acc[ii][1] = ffma2(a.x, b0.y, acc[ii][1]);
            acc[ii][0] = ffma2(a.y, b1.x, acc[ii][0]);
            acc[ii][1] = ffma2(a.y, b1.y, acc[ii][1]);
        }
    }
    __syncthreads();

    float bb0 = sBa[4 * tx + 0], bb1 = sBa[4 * tx + 1];
    float bb2 = sBa[4 * tx + 2], bb3 = sBa[4 * tx + 3];
#pragma unroll
    for (int ii = 0; ii < 8; ii++) {
        int e = ty + 16 * ii;
        float h0 = sspf(f2lo(acc[ii][0]) + bb0);
        float h1 = sspf(f2hi(acc[ii][0]) + bb1);
        float h2 = sspf(f2lo(acc[ii][1]) + bb2);
        float h3 = sspf(f2hi(acc[ii][1]) + bb3);
        float2* p = (float2*)&sA[e * 128 + 8 * tx];
        p[0] = make_float2(h0, h0);
        p[1] = make_float2(h1, h1);
        p[2] = make_float2(h2, h2);
        p[3] = make_float2(h3, h3);
    }
    __syncthreads();

    ull wacc[8][2];
#pragma unroll
    for (int ii = 0; ii < 8; ii++) { wacc[ii][0] = 0ull; wacc[ii][1] = 0ull; }
#pragma unroll
    for (int p = 0; p < 32; p++) {
        ulonglong2 b0 = *reinterpret_cast<const ulonglong2*>(&sWbt[(2 * p) * 64 + 4 * tx]);
        ulonglong2 b1 = *reinterpret_cast<const ulonglong2*>(&sWbt[(2 * p + 1) * 64 + 4 * tx]);
#pragma unroll
        for (int ii = 0; ii < 8; ii++) {
            ulonglong2 a = *reinterpret_cast<const ulonglong2*>(&sA[(ty + 16 * ii) * 128 + 4 * p]);
            wacc[ii][0] = ffma2(a.x, b0.x, wacc[ii][0]);
            wacc[ii][1] = ffma2(a.x, b0.y, wacc[ii][1]);
            wacc[ii][0] = ffma2(a.y, b1.x, wacc[ii][0]);
            wacc[ii][1] = ffma2(a.y, b1.y, wacc[ii][1]);
        }
    }

    float c0 = sBb[4 * tx + 0], c1 = sBb[4 * tx + 1];
    float c2 = sBb[4 * tx + 2], c3 = sBb[4 * tx + 3];
    float ps0 = 0.f, ps1 = 0.f, ps2 = 0.f, ps3 = 0.f;
    float pq0 = 0.f, pq1 = 0.f, pq2 = 0.f, pq3 = 0.f;
#pragma unroll
    for (int ii = 0; ii < 8; ii++) {
        int n = n0 + ty + 16 * ii;
        if (n < N_NODES) {
            float4 prev = *(const float4*)&g_out[n * D1 + 4 * tx];
            float r0 = f2lo(wacc[ii][0]) + c0 + prev.x;
            float r1 = f2hi(wacc[ii][0]) + c1 + prev.y;
            float r2 = f2lo(wacc[ii][1]) + c2 + prev.z;
            float r3 = f2hi(wacc[ii][1]) + c3 + prev.w;
            float4 o; o.x = r0; o.y = r1; o.z = r2; o.w = r3;
            *(float4*)&g_out[n * D1 + 4 * tx] = o;
            ps0 += r0; ps1 += r1; ps2 += r2; ps3 += r3;
            pq0 += r0 * r0; pq1 += r1 * r1; pq2 += r2 * r2; pq3 += r3 * r3;
        }
    }
    atomicAdd(&sSum[4 * tx + 0], ps0); atomicAdd(&sSum[4 * tx + 1], ps1);
    atomicAdd(&sSum[4 * tx + 2], ps2); atomicAdd(&sSum[4 * tx + 3], ps3);
    atomicAdd(&sSq[4 * tx + 0], pq0);  atomicAdd(&sSq[4 * tx + 1], pq1);
    atomicAdd(&sSq[4 * tx + 2], pq2);  atomicAdd(&sSq[4 * tx + 3], pq3);
    __syncthreads();
    if (tid < 64) {
        atomicAdd(&g_bnstats[tid], sSum[tid]);
        atomicAdd(&g_bnstats[64 + tid], sSq[tid]);
    }
}

// =====================================================================
// pool with fused layer-2 BN
// =====================================================================
__global__ __launch_bounds__(256) void k_pool(const int* __restrict__ batch,
                                              const float* __restrict__ bng,
                                              const float* __restrict__ bnb) {
    __shared__ float sSc[64], sOf[64];
    int tid = threadIdx.x;
    if (tid < 64) {
        const float invN = 1.f / (float)N_NODES;
        float mu = g_bnstats[tid] * invN;
        float var = fmaxf(g_bnstats[64 + tid] * invN - mu * mu, 0.f);
        float sc = rsqrtf(var + BN_EPS) * bng[tid];
        sSc[tid] = sc;
        sOf[tid] = bnb[tid] - mu * sc;
    }
    __syncthreads();
    int idx = blockIdx.x * blockDim.x + tid;
    if (idx >= N_NODES * D1) return;
    int n = idx >> 6, f = idx & 63;
    int bg = batch[n];
    float v = g_out[idx] * sSc[f] + sOf[f];
    atomicAdd(&g_pool[bg * D1 + f], v);
    if (f == 0) atomicAdd(&g_cnt[bg], 1.f);
}

__global__ void k_head(const float* __restrict__ postW, const float* __restrict__ postb,
                       const float* __restrict__ outW, const float* __restrict__ outb,
                       float* __restrict__ y) {
    int g = blockIdx.x;
    int f = threadIdx.x;
    __shared__ float sp[64];
    __shared__ float sr[2];
    float cnt = fmaxf(g_cnt[g], 1.f);
    sp[f] = g_pool[g * D1 + f] / cnt;
    __syncthreads();
    float a = postb[f];
#pragma unroll
    for (int k = 0; k < 64; k++) a = fmaf(sp[k], postW[f * 64 + k], a);
    float hp = fmaxf(a, 0.f) * outW[f];
#pragma unroll
    for (int o = 16; o > 0; o >>= 1) hp += __shfl_down_sync(0xffffffffu, hp, o);
    if ((f & 31) == 0) sr[f >> 5] = hp;
    __syncthreads();
    if (f == 0) y[g] = sr[0] + sr[1] + outb[0];
}

// =====================================================================
extern "C" void kernel_launch(void* const* d_in, const int* in_sizes, int n_in,
                              void* d_out, int out_size) {
    const float* x      = (const float*)d_in[0];
    const float* ew     = (const float*)d_in[1];
    const float* ea     = (const float*)d_in[2];
    const int*   ei     = (const int*)d_in[3];
    const int*   batch  = (const int*)d_in[4];
    const float* pre_W  = (const float*)d_in[5];
    const float* pre_b  = (const float*)d_in[6];
    const float* mlp_W1 = (const float*)d_in[7];
    const float* mlp_b1 = (const float*)d_in[8];
    const float* mlp_W2 = (const float*)d_in[9];
    const float* mlp_b2 = (const float*)d_in[10];
    const float* cf_W1  = (const float*)d_in[11];
    const float* cf_W2  = (const float*)d_in[12];
    const float* cf_b2  = (const float*)d_in[13];
    const float* int_W  = (const float*)d_in[14];
    const float* int_b  = (const float*)d_in[15];
    const float* bn_g   = (const float*)d_in[16];
    const float* bn_b   = (const float*)d_in[17];
    const float* post_W = (const float*)d_in[18];
    const float* post_b = (const float*)d_in[19];
    const float* out_W  = (const float*)d_in[20];
    const float* out_b  = (const float*)d_in[21];
    float* y = (float*)d_out;

    void *agg_p, *bn_p, *pool_p, *cnt_p, *hist_p;
    cudaGetSymbolAddress(&agg_p, g_agg);
    cudaGetSymbolAddress(&bn_p, g_bnstats);
    cudaGetSymbolAddress(&pool_p, g_pool);
    cudaGetSymbolAddress(&cnt_p, g_cnt);
    cudaGetSymbolAddress(&hist_p, g_hist);

    cudaFuncSetAttribute(k_edge, cudaFuncAttributeMaxDynamicSharedMemorySize, EDGE_SMEM);
    cudaFuncSetAttribute(k_node, cudaFuncAttributeMaxDynamicSharedMemorySize, NODE_SMEM);
    cudaFuncSetAttribute(k_lin1, cudaFuncAttributeMaxDynamicSharedMemorySize, LIN1_SMEM);

    // counting sort of edges by dst + sorted meta
    cudaMemsetAsync(hist_p, 0, N_NODES * sizeof(int));
    k_hist<<<(N_EDGES + 255) / 256, 256>>>(ei);
    k_scan<<<1, 1024>>>();
    k_scatter<<<(N_EDGES + 255) / 256, 256>>>(ei);
    k_permute_meta<<<(N_EDGES + 255) / 256, 256>>>(ei, ew);

    k_pre<<<512, 256>>>(x, pre_W, pre_b);
    cudaMemsetAsync(pool_p, 0, N_GRAPHS * D1 * sizeof(float));
    cudaMemsetAsync(cnt_p, 0, N_GRAPHS * sizeof(float));

    for (int l = 0; l < 3; l++) {
        k_lin1<<<(N_NODES + 127) / 128, 256, LIN1_SMEM>>>(
            cf_W1 + l * 64 * 64,
            bn_g + (l > 0 ? (l - 1) * 64 : 0),
            bn_b + (l > 0 ? (l - 1) * 64 : 0),
            l > 0 ? 1 : 0);
        cudaMemsetAsync(agg_p, 0, (size_t)N_NODES * D1 * sizeof(float));
        cudaMemsetAsync(bn_p, 0, 2 * D1 * sizeof(float));
        k_edge<<<EDGE_GRID, 256, EDGE_SMEM>>>(ea,
                                              mlp_W1 + l * 64 * 50, mlp_b1 + l * 64,
                                              mlp_W2 + l * 64 * 64, mlp_b2 + l * 64);
        k_node<<<(N_NODES + 127) / 128, 256, NODE_SMEM>>>(cf_W2 + l * 64 * 64, cf_b2 + l * 64,
                                                          int_W + l * 64 * 64, int_b + l * 64);
    }

    k_pool<<<(N_NODES * D1 + 255) / 256, 256>>>(batch, bn_g + 2 * 64, bn_b + 2 * 64);
    k_head<<<N_GRAPHS, 64>>>(post_W, post_b, out_W, out_b, y);
}

// round 7
// speedup vs baseline: 2.1984x; 1.0451x over previous
#include <cuda_runtime.h>
#include <math_constants.h>

#define N_NODES 50000
#define N_EDGES 1200000
#define N_GRAPHS 512
#define D1 64
#define NF 92
#define NG 50
#define BN_EPS 1e-5f
#define LOG2F_C 0.6931471805599453f

#define N_TILES (N_EDGES / 128)   // 9375
#define EDGE_GRID 296             // 2 CTAs/SM * 148

typedef unsigned long long ull;

// -------------------- device scratch --------------------
__device__ float g_out[N_NODES * D1];
__device__ float g_h[N_NODES * D1];
__device__ float g_agg[N_NODES * D1];
__device__ float g_bnstats[2 * D1];
__device__ float g_pool[N_GRAPHS * D1];
__device__ float g_cnt[N_GRAPHS];
__device__ int   g_hist[N_NODES];
__device__ int   g_eperm[N_EDGES];
__device__ float g_Cs[N_EDGES];
__device__ int   g_srcs[N_EDGES];
__device__ int   g_dsts[N_EDGES];

// -------------------- helpers --------------------
__device__ __forceinline__ ull ffma2(ull a, ull b, ull c) {
    ull d;
    asm("fma.rn.f32x2 %0, %1, %2, %3;" : "=l"(d) : "l"(a), "l"(b), "l"(c));
    return d;
}
__device__ __forceinline__ ull dup2(float v) {
    ull r;
    asm("mov.b64 %0, {%1, %1};" : "=l"(r) : "f"(v));
    return r;
}
__device__ __forceinline__ float f2lo(ull v) { return __uint_as_float((unsigned)(v & 0xffffffffull)); }
__device__ __forceinline__ float f2hi(ull v) { return __uint_as_float((unsigned)(v >> 32)); }

__device__ __forceinline__ float sspf(float v) {
    return fmaxf(v, 0.f) + __logf(1.f + __expf(-fabsf(v))) - LOG2F_C;
}

__device__ __forceinline__ void red4(float* p, float4 v) {
    asm volatile("red.global.add.v4.f32 [%0], {%1,%2,%3,%4};"
                 :: "l"(p), "f"(v.x), "f"(v.y), "f"(v.z), "f"(v.w) : "memory");
}

__device__ __forceinline__ void cp8(unsigned dst, const void* src) {
    asm volatile("cp.async.ca.shared.global [%0], [%1], 8;" :: "r"(dst), "l"(src));
}
__device__ __forceinline__ void cp_commit() {
    asm volatile("cp.async.commit_group;" ::: "memory");
}
__device__ __forceinline__ void cp_wait0() {
    asm volatile("cp.async.wait_group 0;" ::: "memory");
}
__device__ __forceinline__ unsigned tf32bits(float v) {
    unsigned r;
    asm("cvt.rna.tf32.f32 %0, %1;" : "=r"(r) : "f"(v));
    return r;
}
__device__ __forceinline__ void mma_tf32(float& c0, float& c1, float& c2, float& c3,
                                         unsigned a0, unsigned a1, unsigned a2, unsigned a3,
                                         unsigned b0, unsigned b1) {
    asm volatile("mma.sync.aligned.m16n8k8.row.col.f32.tf32.tf32.f32 "
                 "{%0,%1,%2,%3}, {%4,%5,%6,%7}, {%8,%9}, {%0,%1,%2,%3};"
                 : "+f"(c0), "+f"(c1), "+f"(c2), "+f"(c3)
                 : "r"(a0), "r"(a1), "r"(a2), "r"(a3), "r"(b0), "r"(b1));
}

// =====================================================================
// counting sort by dst
// =====================================================================
__global__ void k_hist(const int* __restrict__ ei) {
    int i = blockIdx.x * blockDim.x + threadIdx.x;
    if (i < N_EDGES) atomicAdd(&g_hist[ei[N_EDGES + i]], 1);
}

__global__ __launch_bounds__(1024) void k_scan() {
    __shared__ int ss[1024];
    int t = threadIdx.x;
    int lo = t * 49;
    int hi = min(lo + 49, N_NODES);
    int s = 0;
    for (int b = lo; b < hi; b++) s += g_hist[b];
    ss[t] = s;
    __syncthreads();
    for (int off = 1; off < 1024; off <<= 1) {
        int v = (t >= off) ? ss[t - off] : 0;
        __syncthreads();
        ss[t] += v;
        __syncthreads();
    }
    int run = ss[t] - s;
    for (int b = lo; b < hi; b++) {
        int c = g_hist[b];
        g_hist[b] = run;
        run += c;
    }
}

__global__ void k_scatter(const int* __restrict__ ei) {
    int i = blockIdx.x * blockDim.x + threadIdx.x;
    if (i < N_EDGES) {
        int pos = atomicAdd(&g_hist[ei[N_EDGES + i]], 1);
        g_eperm[pos] = i;
    }
}

__global__ void k_permute_meta(const int* __restrict__ ei, const float* __restrict__ ew) {
    int e = blockIdx.x * blockDim.x + threadIdx.x;
    if (e >= N_EDGES) return;
    int id = g_eperm[e];
    g_Cs[e] = 0.5f * (cospif(ew[id] * 0.125f) + 1.f);
    g_srcs[e] = ei[id];
    g_dsts[e] = ei[N_EDGES + id];
}

// =====================================================================
// pre FC v2 (block-tile f32x2 GEMM): out = relu(x @ pre_W.T + pre_b)
// K=92. sA stride 94 (4-row groups land on distinct banks).
// =====================================================================
#define PRE_SMEM ((5888 + 12032 + 64) * 4)
__global__ __launch_bounds__(256, 2) void k_pre(const float* __restrict__ x,
                                                const float* __restrict__ W,
                                                const float* __restrict__ b) {
    extern __shared__ float sm[];
    float* sWt = sm;            // [92][64] k-major
    float* sA = sm + 5888;      // [128][94]
    float* sB = sm + 17920;     // [64]

    int tid = threadIdx.x;
    int tx = tid & 7, ty = tid >> 3;
    int n0 = blockIdx.x * 128;

    for (int i = tid; i < 92 * 64; i += 256) {
        int f = i / 92, k = i - f * 92;
        sWt[k * 64 + f] = W[i];
    }
    if (tid < 64) sB[tid] = b[tid];
    for (int i = tid; i < 128 * 92; i += 256) {
        int r = i / 92, k = i - r * 92;
        int n = n0 + r;
        sA[r * 94 + k] = (n < N_NODES) ? x[(size_t)n * NF + k] : 0.f;
    }
    __syncthreads();

    ull acc[4][4];
#pragma unroll
    for (int j = 0; j < 4; j++)
#pragma unroll
        for (int p = 0; p < 4; p++) acc[j][p] = 0ull;

#pragma unroll 4
    for (int k = 0; k < 92; k++) {
        ulonglong2 bA = *(const ulonglong2*)&sWt[k * 64 + 8 * tx];
        ulonglong2 bB = *(const ulonglong2*)&sWt[k * 64 + 8 * tx + 4];
#pragma unroll
        for (int j = 0; j < 4; j++) {
            ull av = dup2(sA[(4 * ty + j) * 94 + k]);
            acc[j][0] = ffma2(av, bA.x, acc[j][0]);
            acc[j][1] = ffma2(av, bA.y, acc[j][1]);
            acc[j][2] = ffma2(av, bB.x, acc[j][2]);
            acc[j][3] = ffma2(av, bB.y, acc[j][3]);
        }
    }

#pragma unroll
    for (int j = 0; j < 4; j++) {
        int n = n0 + 4 * ty + j;
        if (n < N_NODES) {
            float4 o0, o1;
            o0.x = fmaxf(f2lo(acc[j][0]) + sB[8 * tx + 0], 0.f);
            o0.y = fmaxf(f2hi(acc[j][0]) + sB[8 * tx + 1], 0.f);
            o0.z = fmaxf(f2lo(acc[j][1]) + sB[8 * tx + 2], 0.f);
            o0.w = fmaxf(f2hi(acc[j][1]) + sB[8 * tx + 3], 0.f);
            o1.x = fmaxf(f2lo(acc[j][2]) + sB[8 * tx + 4], 0.f);
            o1.y = fmaxf(f2hi(acc[j][2]) + sB[8 * tx + 5], 0.f);
            o1.z = fmaxf(f2lo(acc[j][3]) + sB[8 * tx + 6], 0.f);
            o1.w = fmaxf(f2hi(acc[j][3]) + sB[8 * tx + 7], 0.f);
            *(float4*)&g_out[(size_t)n * D1 + 8 * tx] = o0;
            *(float4*)&g_out[(size_t)n * D1 + 8 * tx + 4] = o1;
        }
    }
}

// =====================================================================
// lin1 (+ fused BN of previous layer)
// =====================================================================
#define LIN1_SMEM ((4096 + 16384 + 192) * 4)
__global__ __launch_bounds__(256, 2) void k_lin1(const float* __restrict__ W,
                                                 const float* __restrict__ bng,
                                                 const float* __restrict__ bnb,
                                                 int apply_bn) {
    extern __shared__ float sm[];
    float* sWt = sm;
    float* sA = sm + 4096;
    float* sSc = sm + 20480;
    float* sOf = sSc + 64;

    int tid = threadIdx.x;
    int tx = tid & 15, ty = tid >> 4;
    int n0 = blockIdx.x * 128;

    for (int i = tid; i < 64 * 64; i += 256) {
        int f = i >> 6, k = i & 63;
        sWt[k * 64 + f] = W[i];
    }
    if (tid < 64 && apply_bn) {
        const float invN = 1.f / (float)N_NODES;
        float mu = g_bnstats[tid] * invN;
        float var = fmaxf(g_bnstats[64 + tid] * invN - mu * mu, 0.f);
        float sc = rsqrtf(var + BN_EPS) * bng[tid];
        sSc[tid] = sc;
        sOf[tid] = bnb[tid] - mu * sc;
    }
    __syncthreads();

    for (int i = tid; i < 128 * 64; i += 256) {
        int e = i >> 6, k = i & 63;
        int n = n0 + e;
        float v = 0.f;
        if (n < N_NODES) {
            v = g_out[n * D1 + k];
            if (apply_bn) {
                v = v * sSc[k] + sOf[k];
                g_out[n * D1 + k] = v;
            }
        }
        *(float2*)&sA[e * 128 + 2 * k] = make_float2(v, v);
    }
    __syncthreads();

    ull acc[8][2];
#pragma unroll
    for (int ii = 0; ii < 8; ii++) { acc[ii][0] = 0ull; acc[ii][1] = 0ull; }
#pragma unroll
    for (int p = 0; p < 32; p++) {
        ulonglong2 b0 = *reinterpret_cast<const ulonglong2*>(&sWt[(2 * p) * 64 + 4 * tx]);
        ulonglong2 b1 = *reinterpret_cast<const ulonglong2*>(&sWt[(2 * p + 1) * 64 + 4 * tx]);
#pragma unroll
        for (int ii = 0; ii < 8; ii++) {
            ulonglong2 a = *reinterpret_cast<const ulonglong2*>(&sA[(ty + 16 * ii) * 128 + 4 * p]);
            acc[ii][0] = ffma2(a.x, b0.x, acc[ii][0]);
            acc[ii][1] = ffma2(a.x, b0.y, acc[ii][1]);
            acc[ii][0] = ffma2(a.y, b1.x, acc[ii][0]);
            acc[ii][1] = ffma2(a.y, b1.y, acc[ii][1]);
        }
    }
#pragma unroll
    for (int ii = 0; ii < 8; ii++) {
        int n = n0 + ty + 16 * ii;
        if (n < N_NODES) {
            float4 o;
            o.x = f2lo(acc[ii][0]); o.y = f2hi(acc[ii][0]);
            o.z = f2lo(acc[ii][1]); o.w = f2hi(acc[ii][1]);
            *(float4*)&g_h[n * D1 + 4 * tx] = o;
        }
    }
}

// =====================================================================
// k_edge v7: tf32 mma pipeline with dedicated sEA buffer so the next
// tile's cp.async fill is issued right after GEMM1 and hides behind
// ssp+GEMM2+scatter. 2 CTAs/SM (no reg cap spills).
//   sEA stride 60 (60%32=28 -> A-frag conflict-free); sHid stride 68.
// =====================================================================
#define EDGE_SW1   0
#define EDGE_SW2   3808               // 56*68
#define EDGE_SEA   8160               // +64*68
#define EDGE_HID   15840              // +128*60
#define EDGE_B1    24544              // +128*68
#define EDGE_B2    24608
#define EDGE_SMEM_WORDS 24672
#define EDGE_SMEM (EDGE_SMEM_WORDS * 4)

__global__ __launch_bounds__(256, 2) void k_edge(const float* __restrict__ EA,
                                                 const float* __restrict__ W1,
                                                 const float* __restrict__ bias1,
                                                 const float* __restrict__ W2,
                                                 const float* __restrict__ bias2) {
    extern __shared__ float sm[];
    float* sW1T = sm + EDGE_SW1;   // [56][68] tf32
    float* sW2T = sm + EDGE_SW2;   // [64][68] tf32
    float* sEA  = sm + EDGE_SEA;   // [128][60] EA tile (cols 50..55 stay 0)
    float* sHid = sm + EDGE_HID;   // [128][68] hid / filter
    float* sB1  = sm + EDGE_B1;
    float* sB2  = sm + EDGE_B2;

    int tid = threadIdx.x;
    int lane = tid & 31;
    int w = tid >> 5;
    int g = lane >> 2, t = lane & 3;
    int R0 = 16 * w;

    for (int i = tid; i < 56 * 64; i += 256) {
        int k = i >> 6, f = i & 63;
        float v = (k < 50) ? W1[f * 50 + k] : 0.f;
        sW1T[k * 68 + f] = __uint_as_float(tf32bits(v));
    }
    for (int i = tid; i < 64 * 64; i += 256) {
        int k = i >> 6, f = i & 63;
        sW2T[k * 68 + f] = __uint_as_float(tf32bits(W2[f * 64 + k]));
    }
    if (tid < 64) { sB1[tid] = bias1[tid]; sB2[tid] = bias2[tid]; }
    for (int i = tid; i < 128 * 60; i += 256) sEA[i] = 0.f;
    __syncthreads();

    int frow = lane >> 1, fhalf = lane & 1;
    int koff = fhalf ? 26 : 0;
    int ncp = fhalf ? 12 : 13;
    unsigned fdst = (unsigned)__cvta_generic_to_shared(sEA)
                  + (unsigned)((R0 + frow) * 60 + koff) * 4u;

    const float* aRow0 = sEA + (R0 + g) * 60;
    const float* aRow8 = sEA + (R0 + g + 8) * 60;
    const float* hRow0 = sHid + (R0 + g) * 68;
    const float* hRow8 = sHid + (R0 + g + 8) * 68;

    // prime first tile's fill
    if (blockIdx.x < N_TILES) {
        int nid = __ldg(&g_eperm[blockIdx.x * 128 + R0 + frow]);
        const float* src = EA + (size_t)nid * NG + koff;
        for (int q = 0; q < ncp; q++)
            cp8(fdst + (unsigned)q * 8u, src + 2 * q);
    }
    cp_commit();

    for (int tile = blockIdx.x; tile < N_TILES; tile += EDGE_GRID) {
        int e0 = tile * 128;
        cp_wait0();
        __syncwarp();   // own warp's EA rows visible to all lanes

        // ---- GEMM1: hid = EA @ W1T, K=56 ----
        float c[8][4];
#pragma unroll
        for (int nb = 0; nb < 8; nb++)
#pragma unroll
            for (int q = 0; q < 4; q++) c[nb][q] = 0.f;

#pragma unroll
        for (int kk = 0; kk < 7; kk++) {
            int kb = kk * 8;
            unsigned a0 = tf32bits(aRow0[kb + t]);
            unsigned a1 = tf32bits(aRow8[kb + t]);
            unsigned a2 = tf32bits(aRow0[kb + t + 4]);
            unsigned a3 = tf32bits(aRow8[kb + t + 4]);
#pragma unroll
            for (int nb = 0; nb < 8; nb++) {
                unsigned b0 = __float_as_uint(sW1T[(kb + t) * 68 + nb * 8 + g]);
                unsigned b1 = __float_as_uint(sW1T[(kb + t + 4) * 68 + nb * 8 + g]);
                mma_tf32(c[nb][0], c[nb][1], c[nb][2], c[nb][3], a0, a1, a2, a3, b0, b1);
            }
        }
        __syncwarp();   // warp done reading its sEA rows

        // ---- eagerly fill NEXT tile's EA rows (hides behind rest of tile) ----
        {
            int ntile = tile + EDGE_GRID;
            if (ntile < N_TILES) {
                int nid = __ldg(&g_eperm[ntile * 128 + R0 + frow]);
                const float* src = EA + (size_t)nid * NG + koff;
                for (int q = 0; q < ncp; q++)
                    cp8(fdst + (unsigned)q * 8u, src + 2 * q);
            }
            cp_commit();
        }

        // ---- ssp + bias -> sHid ----
#pragma unroll
        for (int nb = 0; nb < 8; nb++) {
            int col = nb * 8 + 2 * t;
            float bl = sB1[col], bh = sB1[col + 1];
            *(float2*)&sHid[(R0 + g) * 68 + col] =
                make_float2(sspf(c[nb][0] + bl), sspf(c[nb][1] + bh));
            *(float2*)&sHid[(R0 + g + 8) * 68 + col] =
                make_float2(sspf(c[nb][2] + bl), sspf(c[nb][3] + bh));
        }
        __syncwarp();

        // ---- GEMM2: Wf = hid @ W2T, K=64 ----
        float d[8][4];
#pragma unroll
        for (int nb = 0; nb < 8; nb++)
#pragma unroll
            for (int q = 0; q < 4; q++) d[nb][q] = 0.f;

#pragma unroll
        for (int kk = 0; kk < 8; kk++) {
            int kb = kk * 8;
            unsigned a0 = tf32bits(hRow0[kb + t]);
            unsigned a1 = tf32bits(hRow8[kb + t]);
            unsigned a2 = tf32bits(hRow0[kb + t + 4]);
            unsigned a3 = tf32bits(hRow8[kb + t + 4]);
#pragma unroll
            for (int nb = 0; nb < 8; nb++) {
                unsigned b0 = __float_as_uint(sW2T[(kb + t) * 68 + nb * 8 + g]);
                unsigned b1 = __float_as_uint(sW2T[(kb + t + 4) * 68 + nb * 8 + g]);
                mma_tf32(d[nb][0], d[nb][1], d[nb][2], d[nb][3], a0, a1, a2, a3, b0, b1);
            }
        }
        __syncwarp();

        // ---- store filter back to sHid ----
#pragma unroll
        for (int nb = 0; nb < 8; nb++) {
            int col = nb * 8 + 2 * t;
            *(float2*)&sHid[(R0 + g) * 68 + col] = make_float2(d[nb][0], d[nb][1]);
            *(float2*)&sHid[(R0 + g + 8) * 68 + col] = make_float2(d[nb][2], d[nb][3]);
        }
        __syncwarp();

        // ---- scatter: bias + cutoff + gather h[src] + run-compressed red.v4 ----
        {
            int g2 = lane >> 3, tx = lane & 7;
            float4 bb0 = *(const float4*)&sB2[8 * tx];
            float4 bb1 = *(const float4*)&sB2[8 * tx + 4];
            int cur = -1;
            float4 r0 = make_float4(0.f, 0.f, 0.f, 0.f);
            float4 r1 = make_float4(0.f, 0.f, 0.f, 0.f);
#pragma unroll
            for (int j = 0; j < 4; j++) {
                int le = R0 + 4 * g2 + j;
                int ge = e0 + le;
                float cc = __ldg(&g_Cs[ge]);
                int sn = __ldg(&g_srcs[ge]);
                int dn = __ldg(&g_dsts[ge]);
                float4 w0 = *(const float4*)&sHid[le * 68 + 8 * tx];
                float4 w1 = *(const float4*)&sHid[le * 68 + 8 * tx + 4];
                float4 h0 = *(const float4*)&g_h[(size_t)sn * D1 + 8 * tx];
                float4 h1 = *(const float4*)&g_h[(size_t)sn * D1 + 8 * tx + 4];
                float4 m0, m1;
                m0.x = (w0.x + bb0.x) * cc * h0.x;
                m0.y = (w0.y + bb0.y) * cc * h0.y;
                m0.z = (w0.z + bb0.z) * cc * h0.z;
                m0.w = (w0.w + bb0.w) * cc * h0.w;
                m1.x = (w1.x + bb1.x) * cc * h1.x;
                m1.y = (w1.y + bb1.y) * cc * h1.y;
                m1.z = (w1.z + bb1.z) * cc * h1.z;
                m1.w = (w1.w + bb1.w) * cc * h1.w;
                if (j == 0) {
                    cur = dn; r0 = m0; r1 = m1;
                } else if (dn == cur) {
                    r0.x += m0.x; r0.y += m0.y; r0.z += m0.z; r0.w += m0.w;
                    r1.x += m1.x; r1.y += m1.y; r1.z += m1.z; r1.w += m1.w;
                } else {
                    red4(&g_agg[(size_t)cur * D1 + 8 * tx], r0);
                    red4(&g_agg[(size_t)cur * D1 + 8 * tx + 4], r1);
                    cur = dn; r0 = m0; r1 = m1;
                }
            }
            red4(&g_agg[(size_t)cur * D1 + 8 * tx], r0);
            red4(&g_agg[(size_t)cur * D1 + 8 * tx + 4], r1);
        }
        __syncwarp();
    }
}

// =====================================================================
// node kernel
// =====================================================================
#define NODE_SMEM ((4096 + 4096 + 16384 + 64 + 64 + 64 + 64) * 4)
__global__ __launch_bounds__(256, 2) void k_node(const float* __restrict__ Wa,
                                                 const float* __restrict__ ba,
                                                 const float* __restrict__ Wb,
                                                 const float* __restrict__ bb) {
    extern __shared__ float sm[];
    float* sWat = sm;
    float* sWbt = sm + 4096;
    float* sA = sm + 8192;
    float* sBa = sm + 24576;
    float* sBb = sBa + 64;
    float* sSum = sBb + 64;
    float* sSq = sSum + 64;

    int tid = threadIdx.x;
    int tx = tid & 15, ty = tid >> 4;
    int n0 = blockIdx.x * 128;

    for (int i = tid; i < 64 * 64; i += 256) {
        int f = i >> 6, k = i & 63;
        sWat[k * 64 + f] = Wa[i];
        sWbt[k * 64 + f] = Wb[i];
    }
    if (tid < 64) { sBa[tid] = ba[tid]; sBb[tid] = bb[tid]; sSum[tid] = 0.f; sSq[tid] = 0.f; }
    for (int i = tid; i < 128 * 64; i += 256) {
        int e = i >> 6, k = i & 63;
        int n = n0 + e;
        float v = (n < N_NODES) ? g_agg[n * D1 + k] : 0.f;
        *(float2*)&sA[e * 128 + 2 * k] = make_float2(v, v);
    }
    __syncthreads();

    ull acc[8][2];
#pragma unroll
    for (int ii = 0; ii < 8; ii++) { acc[ii][0] = 0ull; acc[ii][1] = 0ull; }
#pragma unroll
    for (int p = 0; p < 32; p++) {
        ulonglong2 b0 = *reinterpret_cast<const ulonglong2*>(&sWat[(2 * p) * 64 + 4 * tx]);
        ulonglong2 b1 = *reinterpret_cast<const ulonglong2*>(&sWat[(2 * p + 1) * 64 + 4 * tx]);
#pragma unroll
        for (int ii = 0; ii < 8; ii++) {
            ulonglong2 a = *reinterpret_cast<const ulonglong2*>(&sA[(ty + 16 * ii) * 128 + 4 * p]);
            acc[ii][0] = ffma2(a.x, b0.x, acc[ii][0]);
            acc[ii][1] = ffma2(a.x, b0.y, acc[ii][1]);
            acc[ii][0] = ffma2(a.y, b1.x, acc[ii][0]);
            acc[ii][1] = ffma2(a.y, b1.y, acc[ii][1]);
        }
    }
    __syncthreads();

    float bb0 = sBa[4 * tx + 0], bb1 = sBa[4 * tx + 1];
    float bb2 = sBa[4 * tx + 2], bb3 = sBa[4 * tx + 3];
#pragma unroll
    for (int ii = 0; ii < 8; ii++) {
        int e = ty + 16 * ii;
        float h0 = sspf(f2lo(acc[ii][0]) + bb0);
        float h1 = sspf(f2hi(acc[ii][0]) + bb1);
        float h2 = sspf(f2lo(acc[ii][1]) + bb2);
        float h3 = sspf(f2hi(acc[ii][1]) + bb3);
        float2* p = (float2*)&sA[e * 128 + 8 * tx];
        p[0] = make_float2(h0, h0);
        p[1] = make_float2(h1, h1);
        p[2] = make_float2(h2, h2);
        p[3] = make_float2(h3, h3);
    }
    __syncthreads();

    ull wacc[8][2];
#pragma unroll
    for (int ii = 0; ii < 8; ii++) { wacc[ii][0] = 0ull; wacc[ii][1] = 0ull; }
#pragma unroll
    for (int p = 0; p < 32; p++) {
        ulonglong2 b0 = *reinterpret_cast<const ulonglong2*>(&sWbt[(2 * p) * 64 + 4 * tx]);
        ulonglong2 b1 = *reinterpret_cast<const ulonglong2*>(&sWbt[(2 * p + 1) * 64 + 4 * tx]);
#pragma unroll
        for (int ii = 0; ii < 8; ii++) {
            ulonglong2 a = *reinterpret_cast<const ulonglong2*>(&sA[(ty + 16 * ii) * 128 + 4 * p]);
            wacc[ii][0] = ffma2(a.x, b0.x, wacc[ii][0]);
            wacc[ii][1] = ffma2(a.x, b0.y, wacc[ii][1]);
            wacc[ii][0] = ffma2(a.y, b1.x, wacc[ii][0]);
            wacc[ii][1] = ffma2(a.y, b1.y, wacc[ii][1]);
        }
    }

    float c0 = sBb[4 * tx + 0], c1 = sBb[4 * tx + 1];
    float c2 = sBb[4 * tx + 2], c3 = sBb[4 * tx + 3];
    float ps0 = 0.f, ps1 = 0.f, ps2 = 0.f, ps3 = 0.f;
    float pq0 = 0.f, pq1 = 0.f, pq2 = 0.f, pq3 = 0.f;
#pragma unroll
    for (int ii = 0; ii < 8; ii++) {
        int n = n0 + ty + 16 * ii;
        if (n < N_NODES) {
            float4 prev = *(const float4*)&g_out[n * D1 + 4 * tx];
            float r0 = f2lo(wacc[ii][0]) + c0 + prev.x;
            float r1 = f2hi(wacc[ii][0]) + c1 + prev.y;
            float r2 = f2lo(wacc[ii][1]) + c2 + prev.z;
            float r3 = f2hi(wacc[ii][1]) + c3 + prev.w;
            float4 o; o.x = r0; o.y = r1; o.z = r2; o.w = r3;
            *(float4*)&g_out[n * D1 + 4 * tx] = o;
            ps0 += r0; ps1 += r1; ps2 += r2; ps3 += r3;
            pq0 += r0 * r0; pq1 += r1 * r1; pq2 += r2 * r2; pq3 += r3 * r3;
        }
    }
    atomicAdd(&sSum[4 * tx + 0], ps0); atomicAdd(&sSum[4 * tx + 1], ps1);
    atomicAdd(&sSum[4 * tx + 2], ps2); atomicAdd(&sSum[4 * tx + 3], ps3);
    atomicAdd(&sSq[4 * tx + 0], pq0);  atomicAdd(&sSq[4 * tx + 1], pq1);
    atomicAdd(&sSq[4 * tx + 2], pq2);  atomicAdd(&sSq[4 * tx + 3], pq3);
    __syncthreads();
    if (tid < 64) {
        atomicAdd(&g_bnstats[tid], sSum[tid]);
        atomicAdd(&g_bnstats[64 + tid], sSq[tid]);
    }
}

// =====================================================================
// pool with fused layer-2 BN
// =====================================================================
__global__ __launch_bounds__(256) void k_pool(const int* __restrict__ batch,
                                              const float* __restrict__ bng,
                                              const float* __restrict__ bnb) {
    __shared__ float sSc[64], sOf[64];
    int tid = threadIdx.x;
    if (tid < 64) {
        const float invN = 1.f / (float)N_NODES;
        float mu = g_bnstats[tid] * invN;
        float var = fmaxf(g_bnstats[64 + tid] * invN - mu * mu, 0.f);
        float sc = rsqrtf(var + BN_EPS) * bng[tid];
        sSc[tid] = sc;
        sOf[tid] = bnb[tid] - mu * sc;
    }
    __syncthreads();
    int idx = blockIdx.x * blockDim.x + tid;
    if (idx >= N_NODES * D1) return;
    int n = idx >> 6, f = idx & 63;
    int bg = batch[n];
    float v = g_out[idx] * sSc[f] + sOf[f];
    atomicAdd(&g_pool[bg * D1 + f], v);
    if (f == 0) atomicAdd(&g_cnt[bg], 1.f);
}

__global__ void k_head(const float* __restrict__ postW, const float* __restrict__ postb,
                       const float* __restrict__ outW, const float* __restrict__ outb,
                       float* __restrict__ y) {
    int g = blockIdx.x;
    int f = threadIdx.x;
    __shared__ float sp[64];
    __shared__ float sr[2];
    float cnt = fmaxf(g_cnt[g], 1.f);
    sp[f] = g_pool[g * D1 + f] / cnt;
    __syncthreads();
    float a = postb[f];
#pragma unroll
    for (int k = 0; k < 64; k++) a = fmaf(sp[k], postW[f * 64 + k], a);
    float hp = fmaxf(a, 0.f) * outW[f];
#pragma unroll
    for (int o = 16; o > 0; o >>= 1) hp += __shfl_down_sync(0xffffffffu, hp, o);
    if ((f & 31) == 0) sr[f >> 5] = hp;
    __syncthreads();
    if (f == 0) y[g] = sr[0] + sr[1] + outb[0];
}

// =====================================================================
extern "C" void kernel_launch(void* const* d_in, const int* in_sizes, int n_in,
                              void* d_out, int out_size) {
    const float* x      = (const float*)d_in[0];
    const float* ew     = (const float*)d_in[1];
    const float* ea     = (const float*)d_in[2];
    const int*   ei     = (const int*)d_in[3];
    const int*   batch  = (const int*)d_in[4];
    const float* pre_W  = (const float*)d_in[5];
    const float* pre_b  = (const float*)d_in[6];
    const float* mlp_W1 = (const float*)d_in[7];
    const float* mlp_b1 = (const float*)d_in[8];
    const float* mlp_W2 = (const float*)d_in[9];
    const float* mlp_b2 = (const float*)d_in[10];
    const float* cf_W1  = (const float*)d_in[11];
    const float* cf_W2  = (const float*)d_in[12];
    const float* cf_b2  = (const float*)d_in[13];
    const float* int_W  = (const float*)d_in[14];
    const float* int_b  = (const float*)d_in[15];
    const float* bn_g   = (const float*)d_in[16];
    const float* bn_b   = (const float*)d_in[17];
    const float* post_W = (const float*)d_in[18];
    const float* post_b = (const float*)d_in[19];
    const float* out_W  = (const float*)d_in[20];
    const float* out_b  = (const float*)d_in[21];
    float* y = (float*)d_out;

    void *agg_p, *bn_p, *pool_p, *cnt_p, *hist_p;
    cudaGetSymbolAddress(&agg_p, g_agg);
    cudaGetSymbolAddress(&bn_p, g_bnstats);
    cudaGetSymbolAddress(&pool_p, g_pool);
    cudaGetSymbolAddress(&cnt_p, g_cnt);
    cudaGetSymbolAddress(&hist_p, g_hist);

    cudaFuncSetAttribute(k_edge, cudaFuncAttributeMaxDynamicSharedMemorySize, EDGE_SMEM);
    cudaFuncSetAttribute(k_node, cudaFuncAttributeMaxDynamicSharedMemorySize, NODE_SMEM);
    cudaFuncSetAttribute(k_lin1, cudaFuncAttributeMaxDynamicSharedMemorySize, LIN1_SMEM);
    cudaFuncSetAttribute(k_pre, cudaFuncAttributeMaxDynamicSharedMemorySize, PRE_SMEM);

    // counting sort of edges by dst + sorted meta
    cudaMemsetAsync(hist_p, 0, N_NODES * sizeof(int));
    k_hist<<<(N_EDGES + 255) / 256, 256>>>(ei);
    k_scan<<<1, 1024>>>();
    k_scatter<<<(N_EDGES + 255) / 256, 256>>>(ei);
    k_permute_meta<<<(N_EDGES + 255) / 256, 256>>>(ei, ew);

    k_pre<<<(N_NODES + 127) / 128, 256, PRE_SMEM>>>(x, pre_W, pre_b);
    cudaMemsetAsync(pool_p, 0, N_GRAPHS * D1 * sizeof(float));
    cudaMemsetAsync(cnt_p, 0, N_GRAPHS * sizeof(float));

    for (int l = 0; l < 3; l++) {
        k_lin1<<<(N_NODES + 127) / 128, 256, LIN1_SMEM>>>(
            cf_W1 + l * 64 * 64,
            bn_g + (l > 0 ? (l - 1) * 64 : 0),
            bn_b + (l > 0 ? (l - 1) * 64 : 0),
            l > 0 ? 1 : 0);
        cudaMemsetAsync(agg_p, 0, (size_t)N_NODES * D1 * sizeof(float));
        cudaMemsetAsync(bn_p, 0, 2 * D1 * sizeof(float));
        k_edge<<<EDGE_GRID, 256, EDGE_SMEM>>>(ea,
                                              mlp_W1 + l * 64 * 50, mlp_b1 + l * 64,
                                              mlp_W2 + l * 64 * 64, mlp_b2 + l * 64);
        k_node<<<(N_NODES + 127) / 128, 256, NODE_SMEM>>>(cf_W2 + l * 64 * 64, cf_b2 + l * 64,
                                                          int_W + l * 64 * 64, int_b + l * 64);
    }

    k_pool<<<(N_NODES * D1 + 255) / 256, 256>>>(batch, bn_g + 2 * 64, bn_b + 2 * 64);
    k_head<<<N_GRAPHS, 64>>>(post_W, post_b, out_W, out_b, y);
}